// round 13
// baseline (speedup 1.0000x reference)
#include <cuda_runtime.h>
#include <cuda_fp16.h>
#include <cstdint>
#include <math.h>

#define NB 16
#define ND 256
#define NPIX 4096

__device__ float g_spart[NB*8*64*64];
__device__ __align__(16) __half g_attn_h[NB*64*64];
__device__ __align__(16) __half g_attn_l[NB*64*64];

// token-major with PERMUTED e-axis: e' = l*256 + o  (l = in-patch pos, o = channel)
__device__ __align__(16) __half g_qt [NB*64*16384];
__device__ __align__(16) __half g_kt [NB*64*16384];
__device__ __align__(16) __half g_vt [NB*64*16384];
__device__ __align__(16) __half g_vtl[NB*64*16384];
__device__ __align__(16) __half g_xt2 [NB*4*NPIX*64];
__device__ __align__(16) __half g_aot2[NB*4*NPIX*64];
__device__ __align__(16) __half g_wp2 [3*2*4*128*64];
__device__ __align__(16) __half g_wc2 [9*2*4*128*64];

__device__ __forceinline__ uint32_t smem_u32(const void* p){
    uint32_t a;
    asm("{ .reg .u64 t; cvta.to.shared.u64 t, %1; cvt.u32.u64 %0, t; }" : "=r"(a) : "l"(p));
    return a;
}
#define MB_INIT(mb, n) asm volatile("mbarrier.init.shared.b64 [%0], %1;" :: "r"(mb), "r"(n) : "memory")
#define MB_EXPECT(mb, bytes) asm volatile("mbarrier.arrive.expect_tx.shared.b64 _, [%0], %1;" :: "r"(mb), "r"(bytes) : "memory")

__device__ __forceinline__ void bulk_g2s(uint32_t dst, const void* src, uint32_t bytes, uint32_t mbar){
    asm volatile("{ .reg .u64 g; cvta.to.global.u64 g, %1;\n\t"
        "cp.async.bulk.shared::cluster.global.mbarrier::complete_tx::bytes [%0], [g], %2, [%3]; }"
        :: "r"(dst), "l"(src), "r"(bytes), "r"(mbar) : "memory");
}

#define MB_WAIT(mb, ph) do { \
    uint32_t _m = (mb); uint32_t _p = (uint32_t)(ph); uint32_t _d; \
    asm volatile("{\n\t.reg .pred p;\n\t" \
        "mbarrier.try_wait.parity.acquire.cta.shared::cta.b64 p, [%1], %2;\n\t" \
        "selp.b32 %0, 1, 0, p;\n\t}" : "=r"(_d) : "r"(_m), "r"(_p) : "memory"); \
    if (!_d) { \
        asm volatile("{\n\t.reg .pred P1;\n\t" \
            "WAIT_LOOP_%=:\n\t" \
            "mbarrier.try_wait.parity.acquire.cta.shared::cta.b64 P1, [%0], %1, 0x989680;\n\t" \
            "@P1 bra.uni WAIT_DONE_%=;\n\t" \
            "bra.uni WAIT_LOOP_%=;\n\t" \
            "WAIT_DONE_%=:\n\t}" :: "r"(_m), "r"(_p) : "memory"); \
    } \
} while(0)

__device__ __forceinline__ void cp16(uint32_t saddr, const void* gaddr){
    asm volatile("cp.async.ca.shared.global [%0], [%1], 16;"
        :: "r"(saddr), "l"(gaddr));
}
#define CP_COMMIT() asm volatile("cp.async.commit_group;" ::: "memory")
#define CP_WAIT1()  asm volatile("cp.async.wait_group 1;" ::: "memory")
#define CP_WAIT0()  asm volatile("cp.async.wait_group 0;" ::: "memory")

__device__ __forceinline__ void ldmat4(uint32_t* r, uint32_t addr){
    asm volatile("ldmatrix.sync.aligned.m8n8.x4.shared.b16 {%0,%1,%2,%3}, [%4];"
        : "=r"(r[0]), "=r"(r[1]), "=r"(r[2]), "=r"(r[3]) : "r"(addr));
}
__device__ __forceinline__ void ldmat4t(uint32_t* r, uint32_t addr){
    asm volatile("ldmatrix.sync.aligned.m8n8.x4.trans.shared.b16 {%0,%1,%2,%3}, [%4];"
        : "=r"(r[0]), "=r"(r[1]), "=r"(r[2]), "=r"(r[3]) : "r"(addr));
}
__device__ __forceinline__ void mma16816(float* d, const uint32_t* a, const uint32_t* b){
    asm volatile("mma.sync.aligned.m16n8k16.row.col.f32.f16.f16.f32 "
        "{%0,%1,%2,%3}, {%4,%5,%6,%7}, {%8,%9}, {%0,%1,%2,%3};"
        : "+f"(d[0]), "+f"(d[1]), "+f"(d[2]), "+f"(d[3])
        : "r"(a[0]), "r"(a[1]), "r"(a[2]), "r"(a[3]), "r"(b[0]), "r"(b[1]));
}

__global__ void __launch_bounds__(256) convert_x_kernel(const float* __restrict__ xsrc)
{
    const int b = blockIdx.z, c0 = blockIdx.y * 32, p0 = blockIdx.x * 32;
    __shared__ float tile[32][33];
    const int tx = threadIdx.x & 31, ty = threadIdx.x >> 5;
    const float* s = xsrc + ((size_t)b * ND + c0) * NPIX + p0;
    #pragma unroll
    for (int i = 0; i < 32; i += 8)
        tile[ty + i][tx] = s[(size_t)(ty + i) * NPIX + tx];
    __syncthreads();
    const int cc = (threadIdx.x & 15) * 2;
    const int pr = threadIdx.x >> 4;
    #pragma unroll
    for (int pass = 0; pass < 2; pass++) {
        const int prow = pr + pass * 16;
        const int pix = p0 + prow;
        const int c = c0 + cc;
        const int chunk = c >> 6, cl = c & 63;
        size_t di = ((size_t)(b * 4 + chunk) * NPIX + pix) * 64
                  + (((cl >> 3) ^ (pix & 7)) << 3) + (cl & 7);
        *(__half2*)(g_xt2 + di) = __floats2half2_rn(tile[cc][prow], tile[cc + 1][prow]);
    }
}

__global__ void __launch_bounds__(256) convert_wqkv_kernel(
    const float* __restrict__ wq, const float* __restrict__ wk, const float* __restrict__ wv)
{
    int i = blockIdx.x * 256 + threadIdx.x;
    const float* w = (i < 65536) ? wq : (i < 131072) ? wk : wv;
    const float v = w[i & 65535];
    const int proj = i >> 16, r = i & 65535;
    const int o_g = r >> 8, c_g = r & 255;
    const int otile = o_g >> 7, o = o_g & 127, chunk = c_g >> 6, c = c_g & 63;
    const size_t pos = (size_t)(((proj * 2 + otile) * 4 + chunk)) * 8192
                     + (o << 6) + (((c >> 3) ^ (o & 7)) << 3) + (c & 7);
    g_wp2[pos] = __float2half_rn(v);
}

__global__ void __launch_bounds__(256) convert_wconv_kernel(const float* __restrict__ w_out)
{
    int i = blockIdx.x * 256 + threadIdx.x;
    const float v = w_out[i];
    const int o_g = i / 2304;
    const int rem = i - o_g * 2304;
    const int c_g = rem / 9, khw = rem - (rem / 9) * 9;
    const int otile = o_g >> 7, o = o_g & 127, chunk = c_g >> 6, c = c_g & 63;
    const size_t pos = (size_t)(((khw * 2 + otile) * 4 + chunk)) * 8192
                     + (o << 6) + (((c >> 3) ^ (o & 7)) << 3) + (c & 7);
    g_wc2[pos] = __float2half_rn(v);
}

#define QKV_SLOT  32768
#define QKV_SMEM  (1024 + 3*QKV_SLOT)
#define STG_STRIDE 136
#define STG_BYTES  34816

__global__ void __launch_bounds__(256, 2) qkv_mma_kernel(
    const float* __restrict__ bq, const float* __restrict__ bk, const float* __restrict__ bv)
{
    extern __shared__ char smem[];
    const uint32_t sb = smem_u32(smem);
    const uint32_t data = sb + 1024;
    const int tid = threadIdx.x;
    const int lane = tid & 31, wid = tid >> 5;
    const int wm = wid >> 2, wn = wid & 3;
    const int n0 = blockIdx.x * 128;
    const int otile = blockIdx.y, o0 = otile * 128;
    const int bp = blockIdx.z, proj = bp % 3, b = bp / 3;

    const __half* Asrc = g_wp2 + (size_t)((proj * 2 + otile) * 4) * 8192;
    const __half* Bsrc = g_xt2 + ((size_t)(b * 4) * NPIX + n0) * 64;

    if (tid == 0) { MB_INIT(sb, 1); MB_INIT(sb + 8, 1); MB_INIT(sb + 16, 1); }
    __syncthreads();

    auto issue = [&](int s) {
        const uint32_t mb = sb + (s % 3) * 8;
        const uint32_t dst = data + (s % 3) * QKV_SLOT;
        MB_EXPECT(mb, 32768u);
        bulk_g2s(dst,         Asrc + (size_t)s * 8192,      16384u, mb);
        bulk_g2s(dst + 16384, Bsrc + (size_t)s * NPIX * 64, 16384u, mb);
    };
    if (tid == 0) { issue(0); issue(1); issue(2); }

    float acc[4][4][4];
    #pragma unroll
    for (int i = 0; i < 4; i++)
        #pragma unroll
        for (int j = 0; j < 4; j++)
            #pragma unroll
            for (int q = 0; q < 4; q++) acc[i][j][q] = 0.f;

    #pragma unroll 1
    for (int s = 0; s < 4; s++) {
        MB_WAIT(sb + (s % 3) * 8, (s / 3) & 1);
        const uint32_t ab = data + (s % 3) * QKV_SLOT;
        const uint32_t bb = ab + 16384;
        #pragma unroll
        for (int kh = 0; kh < 4; kh++) {
            uint32_t ah[4][4], bf[4][2];
            #pragma unroll
            for (int i = 0; i < 4; i++) {
                const int row = wm * 64 + i * 16 + (lane & 15);
                const int ch = (2 * kh + (lane >> 4)) ^ (row & 7);
                ldmat4(ah[i], ab + row * 128 + ch * 16);
            }
            #pragma unroll
            for (int jj = 0; jj < 2; jj++) {
                const int row = wn * 32 + jj * 16 + (lane & 7) + ((lane >> 4) << 3);
                const int ch = (2 * kh + ((lane >> 3) & 1)) ^ (row & 7);
                uint32_t r4[4];
                ldmat4(r4, bb + row * 128 + ch * 16);
                bf[2*jj][0] = r4[0]; bf[2*jj][1] = r4[1];
                bf[2*jj+1][0] = r4[2]; bf[2*jj+1][1] = r4[3];
            }
            #pragma unroll
            for (int i = 0; i < 4; i++)
                #pragma unroll
                for (int j = 0; j < 4; j++)
                    mma16816(acc[i][j], ah[i], bf[j]);
        }
        __syncthreads();
        if (tid == 0 && s + 3 < 4) issue(s + 3);
    }

    const float* bias = (proj == 0) ? bq : (proj == 1) ? bk : bv;
    const int hh0 = n0 >> 6;
    const int tbase = (hh0 >> 3) << 3;
    const int l0 = (hh0 & 7) << 3;
    __half* stg0 = (__half*)(smem + 1024);
    __half* stg1 = (__half*)(smem + 1024 + STG_BYTES);

    #pragma unroll
    for (int i = 0; i < 4; i++) {
        const int oa = wm * 64 + i * 16 + (lane >> 2);
        const float bb0 = bias[o0 + oa], bb1 = bias[o0 + oa + 8];
        #pragma unroll
        for (int j = 0; j < 4; j++) {
            const int p = n0 + wn * 32 + j * 8 + 2 * (lane & 3);
            const int tloc = (p >> 3) & 7;
            const int lloc = ((p >> 6) & 1) * 8 + (p & 7);
            const int row = tloc * 16 + lloc;
            const float f0 = acc[i][j][0] + bb0, f1 = acc[i][j][1] + bb0;
            const float f2 = acc[i][j][2] + bb1, f3 = acc[i][j][3] + bb1;
            const __half q0 = __float2half_rn(f0), q1 = __float2half_rn(f1);
            const __half q2 = __float2half_rn(f2), q3 = __float2half_rn(f3);
            stg0[row * STG_STRIDE + oa]           = q0;
            stg0[(row + 1) * STG_STRIDE + oa]     = q1;
            stg0[row * STG_STRIDE + oa + 8]       = q2;
            stg0[(row + 1) * STG_STRIDE + oa + 8] = q3;
            if (proj == 2) {
                stg1[row * STG_STRIDE + oa]           = __float2half_rn(f0 - __half2float(q0));
                stg1[(row + 1) * STG_STRIDE + oa]     = __float2half_rn(f1 - __half2float(q1));
                stg1[row * STG_STRIDE + oa + 8]       = __float2half_rn(f2 - __half2float(q2));
                stg1[(row + 1) * STG_STRIDE + oa + 8] = __float2half_rn(f3 - __half2float(q3));
            }
        }
    }
    __syncthreads();

    const int rowi = tid >> 1, half = tid & 1;
    const int t = tbase + (rowi >> 4);
    const int l = l0 + (rowi & 15);
    const size_t gbase = (size_t)t * 16384 + l * 256 + o0 + half * 64;
    if (proj < 2) {
        __half* qt = ((proj == 0) ? g_qt : g_kt) + (size_t)b * 64 * 16384;
        const uint4* src = (const uint4*)(stg0 + rowi * STG_STRIDE + half * 64);
        uint4* dst = (uint4*)(qt + gbase);
        #pragma unroll
        for (int k2 = 0; k2 < 8; k2++) dst[k2] = src[k2];
    } else {
        const uint4* s0 = (const uint4*)(stg0 + rowi * STG_STRIDE + half * 64);
        const uint4* s1 = (const uint4*)(stg1 + rowi * STG_STRIDE + half * 64);
        uint4* d0 = (uint4*)(g_vt  + (size_t)b * 64 * 16384 + gbase);
        uint4* d1 = (uint4*)(g_vtl + (size_t)b * 64 * 16384 + gbase);
        #pragma unroll
        for (int k2 = 0; k2 < 8; k2++) { d0[k2] = s0[k2]; d1[k2] = s1[k2]; }
    }
}

#define SC_STAGE 16384
#define SC_SMEM  (3*SC_STAGE)

__global__ void __launch_bounds__(256, 2) scores_mma_kernel()
{
    extern __shared__ char smem[];
    const uint32_t sbase = smem_u32(smem);
    const int tid = threadIdx.x;
    const int lane = tid & 31, wid = tid >> 5;
    const int wm = wid & 3, wn = wid >> 2;
    const int slice = blockIdx.x, b = blockIdx.y;
    const size_t eoff = (size_t)slice * 2048;

    const __half* Q = g_qt + (size_t)b * 64 * 16384 + eoff;
    const __half* K = g_kt + (size_t)b * 64 * 16384 + eoff;

    auto load_stage = [&](int ck, int buf) {
        const uint32_t stb = sbase + buf * SC_STAGE;
        #pragma unroll
        for (int q = 0; q < 2; q++) {
            const int idx = tid + q * 256;
            const int row = idx >> 3, c = idx & 7;
            const uint32_t so = row * 128 + ((c ^ (row & 7)) << 4);
            const size_t goff = (size_t)row * 16384 + ck * 64 + c * 8;
            cp16(stb + so,        Q + goff);
            cp16(stb + 8192 + so, K + goff);
        }
        CP_COMMIT();
    };

    float acc[4][4];
    #pragma unroll
    for (int j = 0; j < 4; j++)
        #pragma unroll
        for (int q = 0; q < 4; q++) acc[j][q] = 0.f;

    load_stage(0, 0);
    load_stage(1, 1);
    #pragma unroll 1
    for (int s = 0; s < 32; s++) {
        if (s + 1 < 32) { CP_WAIT1(); } else { CP_WAIT0(); }
        __syncthreads();
        if (s + 2 < 32) load_stage(s + 2, (s + 2) % 3);
        const uint32_t qb = sbase + (s % 3) * SC_STAGE;
        const uint32_t kb = qb + 8192;
        #pragma unroll
        for (int kh = 0; kh < 4; kh++) {
            uint32_t ah[4], bf[4][2];
            {
                const int row = wm * 16 + (lane & 15);
                const int ch = (2 * kh + (lane >> 4)) ^ (row & 7);
                ldmat4(ah, qb + row * 128 + ch * 16);
            }
            #pragma unroll
            for (int jj = 0; jj < 2; jj++) {
                const int row = wn * 32 + jj * 16 + (lane & 7) + ((lane >> 4) << 3);
                const int ch = (2 * kh + ((lane >> 3) & 1)) ^ (row & 7);
                uint32_t r4[4];
                ldmat4(r4, kb + row * 128 + ch * 16);
                bf[2*jj][0] = r4[0]; bf[2*jj][1] = r4[1];
                bf[2*jj+1][0] = r4[2]; bf[2*jj+1][1] = r4[3];
            }
            #pragma unroll
            for (int j = 0; j < 4; j++)
                mma16816(acc[j], ah, bf[j]);
        }
        __syncthreads();
    }

    float* dst = g_spart + ((size_t)(b * 8 + slice)) * 4096;
    #pragma unroll
    for (int j = 0; j < 4; j++) {
        const int r0 = wm * 16 + (lane >> 2);
        const int cb = wn * 32 + j * 8 + 2 * (lane & 3);
        *(float2*)(dst + r0 * 64 + cb)       = make_float2(acc[j][0], acc[j][1]);
        *(float2*)(dst + (r0 + 8) * 64 + cb) = make_float2(acc[j][2], acc[j][3]);
    }
}

__global__ void __launch_bounds__(64) softmax_kernel()
{
    const int b = blockIdx.x;
    const int t = threadIdx.x;
    const float scale = 1.0f / 128.0f;
    float v[64];
    #pragma unroll
    for (int u = 0; u < 64; u++) v[u] = 0.f;
    #pragma unroll 2
    for (int sl = 0; sl < 8; sl++) {
        const float* row = g_spart + ((size_t)(b * 8 + sl)) * 4096 + t * 64;
        #pragma unroll
        for (int u = 0; u < 64; u++) v[u] += row[u];
    }
    float m = -1e30f;
    #pragma unroll
    for (int u = 0; u < 64; u++) { v[u] *= scale; m = fmaxf(m, v[u]); }
    float s = 0.f;
    #pragma unroll
    for (int u = 0; u < 64; u++) { v[u] = __expf(v[u] - m); s += v[u]; }
    const float inv = 1.0f / s;
    __half* hrow = g_attn_h + b * 4096 + t * 64;
    __half* lrow = g_attn_l + b * 4096 + t * 64;
    #pragma unroll
    for (int u = 0; u < 64; u += 2) {
        float f0 = v[u] * inv, f1 = v[u+1] * inv;
        __half h0 = __float2half_rn(f0), h1 = __float2half_rn(f1);
        __half2 hh; hh.x = h0; hh.y = h1;
        *(__half2*)(hrow + u) = hh;
        *(__half2*)(lrow + u) = __floats2half2_rn(f0 - __half2float(h0), f1 - __half2float(h1));
    }
}

#define AV_AL   8192
#define AV_VH   16384
#define AV_VL   49152
#define AV_OUT  81920
#define AV_SMEM 114688

__global__ void __launch_bounds__(256, 2) av_mma_kernel()
{
    extern __shared__ char smem[];
    const uint32_t sbase = smem_u32(smem);
    const int tid = threadIdx.x;
    const int lane = tid & 31, wid = tid >> 5;
    const int wm = wid >> 1, wn = wid & 1;
    const int et = blockIdx.x, b = blockIdx.y;   // et = l slice
    const size_t e0 = (size_t)et * 256;

    {
        const __half* Ah = g_attn_h + (size_t)b * 4096;
        const __half* Al = g_attn_l + (size_t)b * 4096;
        const __half* Vh = g_vt  + (size_t)b * 64 * 16384 + e0;
        const __half* Vl = g_vtl + (size_t)b * 64 * 16384 + e0;
        #pragma unroll
        for (int q = 0; q < 2; q++) {
            const int idx = tid + q * 256;
            const int row = idx >> 3, c = idx & 7;
            const uint32_t so = row * 128 + ((c ^ (row & 7)) << 4);
            cp16(sbase + so,         Ah + (size_t)row * 64 + c * 8);
            cp16(sbase + AV_AL + so, Al + (size_t)row * 64 + c * 8);
        }
        #pragma unroll
        for (int q = 0; q < 8; q++) {
            const int idx = tid + q * 256;
            const int row = idx >> 5, c = idx & 31;
            const int sw = (c & 24) | ((c & 7) ^ (row & 7));
            cp16(sbase + AV_VH + row * 512 + sw * 16, Vh + (size_t)row * 16384 + c * 8);
            cp16(sbase + AV_VL + row * 512 + sw * 16, Vl + (size_t)row * 16384 + c * 8);
        }
        CP_COMMIT();
        CP_WAIT0();
    }
    __syncthreads();

    float acc[16][4];
    #pragma unroll
    for (int j = 0; j < 16; j++)
        #pragma unroll
        for (int q = 0; q < 4; q++) acc[j][q] = 0.f;

    #pragma unroll
    for (int kh = 0; kh < 4; kh++) {
        uint32_t ahh[4], ahl[4];
        {
            const int row = wm * 16 + (lane & 15);
            const int ch = (2 * kh + (lane >> 4)) ^ (row & 7);
            ldmat4(ahh, sbase + row * 128 + ch * 16);
            ldmat4(ahl, sbase + AV_AL + row * 128 + ch * 16);
        }
        #pragma unroll
        for (int jj = 0; jj < 8; jj++) {
            const int u = kh * 16 + (lane & 15);
            const int c32 = wn * 16 + jj * 2 + (lane >> 4);
            const int sw = (c32 & 24) | ((c32 & 7) ^ (u & 7));
            uint32_t rh[4], rl[4];
            ldmat4t(rh, sbase + AV_VH + u * 512 + sw * 16);
            ldmat4t(rl, sbase + AV_VL + u * 512 + sw * 16);
            uint32_t bh0[2] = { rh[0], rh[1] }, bh1[2] = { rh[2], rh[3] };
            uint32_t bl0[2] = { rl[0], rl[1] }, bl1[2] = { rl[2], rl[3] };
            mma16816(acc[jj*2],   ahh, bh0);
            mma16816(acc[jj*2],   ahh, bl0);
            mma16816(acc[jj*2],   ahl, bh0);
            mma16816(acc[jj*2],   ahl, bl0);
            mma16816(acc[jj*2+1], ahh, bh1);
            mma16816(acc[jj*2+1], ahh, bl1);
            mma16816(acc[jj*2+1], ahl, bh1);
            mma16816(acc[jj*2+1], ahl, bl1);
        }
    }

    #pragma unroll
    for (int j = 0; j < 16; j++) {
        const int t0 = wm * 16 + (lane >> 2);
        const int e  = wn * 128 + j * 8 + 2 * (lane & 3);
        const int c  = e >> 3;
        const int sw0 = (c & 24) | ((c & 7) ^ (t0 & 7));
        const int sw1 = (c & 24) | ((c & 7) ^ ((t0 + 8) & 7));
        __half2 v0 = __floats2half2_rn(acc[j][0], acc[j][1]);
        __half2 v1 = __floats2half2_rn(acc[j][2], acc[j][3]);
        *(__half2*)(smem + AV_OUT + t0 * 512 + sw0 * 16 + (e & 7) * 2) = v0;
        *(__half2*)(smem + AV_OUT + (t0 + 8) * 512 + sw1 * 16 + (e & 7) * 2) = v1;
    }
    __syncthreads();

    // coalesced scatter: thread = (t, chunk); one 128B conv-layout row each.
    // smem group g = chunk*8 + (k ^ (t&7)) holds channel-group c = chunk*8 + k,
    // so destination offset uses k (channel group), NOT the swizzled group.
    {
        const int t = tid & 63, chunk = tid >> 6;
        const int p = ((t >> 3) * 8 + (et >> 3)) * 64 + (t & 7) * 8 + (et & 7);
        __half* dstrow = g_aot2 + (((size_t)(b * 4 + chunk)) * NPIX + p) * 64;
        #pragma unroll
        for (int k = 0; k < 8; k++) {
            const uint4 v = *(const uint4*)(smem + AV_OUT + t * 512
                             + (chunk * 8 + (k ^ (t & 7))) * 16);
            *(uint4*)(dstrow + ((k ^ (p & 7)) << 3)) = v;
        }
    }
}

#define CV_A_SLOT  16384
#define CV_HALO    (1024 + 3*CV_A_SLOT)
#define CV_SMEM    (CV_HALO + 33792)

__global__ void __launch_bounds__(128, 2) conv_mma_kernel(
    const float* __restrict__ b_out, const float* __restrict__ gamma,
    const float* __restrict__ beta,  const float* __restrict__ bn_mean,
    const float* __restrict__ bn_var, float* __restrict__ out)
{
    extern __shared__ char smem[];
    const uint32_t sb = smem_u32(smem);
    const uint32_t data = sb + 1024;
    const uint32_t halo = sb + CV_HALO;
    const int tid = threadIdx.x;
    const int lane = tid & 31, wid = tid >> 5;
    const int wm = wid >> 1, wn = wid & 1;
    const int pt = blockIdx.x;
    const int otile = blockIdx.y, o0 = otile * 128;
    const int b = blockIdx.z;
    const int h0 = pt * 2, n0 = pt * 128;

    const __half* Bbase = g_aot2 + (size_t)(b * 4) * NPIX * 64;

    if (tid == 0) { MB_INIT(sb, 1); MB_INIT(sb + 8, 1); MB_INIT(sb + 16, 1); MB_INIT(sb + 24, 1); }
    {
        const int4 z = make_int4(0, 0, 0, 0);
        for (int idx = tid; idx < 2112; idx += 128)
            *(int4*)(smem + CV_HALO + idx * 16) = z;
    }
    __syncthreads();

    auto issueA = [&](int s) {
        const int khw = s % 9, chunk = s / 9;
        const uint32_t mb = sb + (s % 3) * 8;
        MB_EXPECT(mb, 16384u);
        bulk_g2s(data + (s % 3) * CV_A_SLOT,
                 g_wc2 + (size_t)((khw * 2 + otile) * 4 + chunk) * 8192, 16384u, mb);
    };
    auto issueHalo = [&](int chunk) {
        const uint32_t mb = sb + 24;
        uint32_t bytes = 0;
        #pragma unroll
        for (int hr = 0; hr < 4; hr++) {
            const int h2 = h0 - 1 + hr;
            if ((unsigned)h2 < 64u) bytes += 8192u;
        }
        MB_EXPECT(mb, bytes);
        #pragma unroll
        for (int hr = 0; hr < 4; hr++) {
            const int h2 = h0 - 1 + hr;
            if ((unsigned)h2 < 64u)
                bulk_g2s(halo + hr * 8448 + 128,
                         Bbase + ((size_t)chunk * NPIX + h2 * 64) * 64, 8192u, mb);
        }
    };
    if (tid == 0) { issueHalo(0); issueA(0); issueA(1); issueA(2); }

    float acc[4][8][4];
    #pragma unroll
    for (int i = 0; i < 4; i++)
        #pragma unroll
        for (int j = 0; j < 8; j++)
            #pragma unroll
            for (int q = 0; q < 4; q++) acc[i][j][q] = 0.f;

    #pragma unroll 1
    for (int s = 0; s < 36; s++) {
        const int khw = s % 9, chunk = s / 9;
        MB_WAIT(sb + (s % 3) * 8, (s / 3) & 1);
        if (khw == 0) MB_WAIT(sb + 24, chunk & 1);
        const int dh = khw / 3 - 1, dw = khw % 3 - 1;
        const uint32_t ab = data + (s % 3) * CV_A_SLOT;
        #pragma unroll
        for (int kh = 0; kh < 4; kh++) {
            uint32_t ah[4][4], bf[8][2];
            #pragma unroll
            for (int i = 0; i < 4; i++) {
                const int row = wm * 64 + i * 16 + (lane & 15);
                const int ch = (2 * kh + (lane >> 4)) ^ (row & 7);
                ldmat4(ah[i], ab + row * 128 + ch * 16);
            }
            #pragma unroll
            for (int jj = 0; jj < 4; jj++) {
                const int p = wn * 64 + jj * 16 + (lane & 7) + ((lane >> 4) << 3);
                const int w2 = (p & 63) + dw;
                const int er = (p >> 6) + dh + 1;
                const int e = er * 66 + w2 + 1;
                const int ch = (2 * kh + ((lane >> 3) & 1)) ^ (w2 & 7);
                uint32_t r4[4];
                ldmat4(r4, halo + e * 128 + ch * 16);
                bf[2*jj][0] = r4[0]; bf[2*jj][1] = r4[1];
                bf[2*jj+1][0] = r4[2]; bf[2*jj+1][1] = r4[3];
            }
            #pragma unroll
            for (int i = 0; i < 4; i++)
                #pragma unroll
                for (int j = 0; j < 8; j++)
                    mma16816(acc[i][j], ah[i], bf[j]);
        }
        __syncthreads();
        if (tid == 0) {
            if (s + 3 < 36) issueA(s + 3);
            if (khw == 8 && chunk < 3) issueHalo(chunk + 1);
        }
    }

    float* dst = out + (size_t)b * ND * NPIX;
    #pragma unroll
    for (int i = 0; i < 4; i++) {
        const int r0 = o0 + wm * 64 + i * 16 + (lane >> 2);
        const float sc0 = gamma[r0]     * rsqrtf(bn_var[r0]     + 1e-5f);
        const float sc1 = gamma[r0 + 8] * rsqrtf(bn_var[r0 + 8] + 1e-5f);
        const float ad0 = (b_out[r0]     - bn_mean[r0])     * sc0 + beta[r0];
        const float ad1 = (b_out[r0 + 8] - bn_mean[r0 + 8]) * sc1 + beta[r0 + 8];
        #pragma unroll
        for (int j = 0; j < 8; j++) {
            const int cb = n0 + wn * 64 + j * 8 + 2 * (lane & 3);
            float t0 = acc[i][j][0] * sc0 + ad0;
            float t1 = acc[i][j][1] * sc0 + ad0;
            float t2 = acc[i][j][2] * sc1 + ad1;
            float t3 = acc[i][j][3] * sc1 + ad1;
            float2 v0 = make_float2((t0 >= 0.f) ? t0 : 0.2f * t0,
                                    (t1 >= 0.f) ? t1 : 0.2f * t1);
            float2 v1 = make_float2((t2 >= 0.f) ? t2 : 0.2f * t2,
                                    (t3 >= 0.f) ? t3 : 0.2f * t3);
            *(float2*)(dst + (size_t)r0 * NPIX + cb) = v0;
            *(float2*)(dst + (size_t)(r0 + 8) * NPIX + cb) = v1;
        }
    }
}

extern "C" void kernel_launch(void* const* d_in, const int* in_sizes, int n_in,
                              void* d_out, int out_size)
{
    const float* x       = (const float*)d_in[0];
    const float* wq      = (const float*)d_in[1];
    const float* bq      = (const float*)d_in[2];
    const float* wk      = (const float*)d_in[3];
    const float* bk      = (const float*)d_in[4];
    const float* wv      = (const float*)d_in[5];
    const float* bv      = (const float*)d_in[6];
    const float* w_out   = (const float*)d_in[7];
    const float* b_out   = (const float*)d_in[8];
    const float* gamma   = (const float*)d_in[9];
    const float* beta    = (const float*)d_in[10];
    const float* bn_mean = (const float*)d_in[11];
    const float* bn_var  = (const float*)d_in[12];
    float* out = (float*)d_out;

    cudaFuncSetAttribute(qkv_mma_kernel,    cudaFuncAttributeMaxDynamicSharedMemorySize, QKV_SMEM);
    cudaFuncSetAttribute(scores_mma_kernel, cudaFuncAttributeMaxDynamicSharedMemorySize, SC_SMEM);
    cudaFuncSetAttribute(av_mma_kernel,     cudaFuncAttributeMaxDynamicSharedMemorySize, AV_SMEM);
    cudaFuncSetAttribute(conv_mma_kernel,   cudaFuncAttributeMaxDynamicSharedMemorySize, CV_SMEM);

    convert_wqkv_kernel <<<768,  256>>>(wq, wk, wv);
    convert_wconv_kernel<<<2304, 256>>>(w_out);
    convert_x_kernel<<<dim3(128, 8, 16), 256>>>(x);

    qkv_mma_kernel<<<dim3(32, 2, 48), 256, QKV_SMEM>>>(bq, bk, bv);

    scores_mma_kernel<<<dim3(8, 16), 256, SC_SMEM>>>();
    softmax_kernel<<<16, 64>>>();
    av_mma_kernel<<<dim3(64, 16), 256, AV_SMEM>>>();

    conv_mma_kernel<<<dim3(32, 2, 16), 128, CV_SMEM>>>(b_out, gamma, beta, bn_mean, bn_var, out);
}

// round 14
// speedup vs baseline: 1.0392x; 1.0392x over previous
#include <cuda_runtime.h>
#include <cuda_fp16.h>
#include <cstdint>
#include <math.h>

#define NB 16
#define ND 256
#define NPIX 4096

__device__ float g_spart[NB*8*64*64];
__device__ __align__(16) __half g_attn_h[NB*64*64];
__device__ __align__(16) __half g_attn_l[NB*64*64];

// token-major, e = o*64 + l  (o = channel, l = in-patch position)  — R11 layout
__device__ __align__(16) __half g_qt [NB*64*16384];
__device__ __align__(16) __half g_kt [NB*64*16384];
__device__ __align__(16) __half g_vt [NB*64*16384];
__device__ __align__(16) __half g_vtl[NB*64*16384];
__device__ __align__(16) __half g_xt2 [NB*4*NPIX*64];
__device__ __align__(16) __half g_aot2[NB*4*NPIX*64];
__device__ __align__(16) __half g_wp2 [3*2*4*128*64];
__device__ __align__(16) __half g_wc2 [9*2*4*128*64];

__device__ __forceinline__ uint32_t smem_u32(const void* p){
    uint32_t a;
    asm("{ .reg .u64 t; cvta.to.shared.u64 t, %1; cvt.u32.u64 %0, t; }" : "=r"(a) : "l"(p));
    return a;
}
#define MB_INIT(mb, n) asm volatile("mbarrier.init.shared.b64 [%0], %1;" :: "r"(mb), "r"(n) : "memory")
#define MB_EXPECT(mb, bytes) asm volatile("mbarrier.arrive.expect_tx.shared.b64 _, [%0], %1;" :: "r"(mb), "r"(bytes) : "memory")

__device__ __forceinline__ void bulk_g2s(uint32_t dst, const void* src, uint32_t bytes, uint32_t mbar){
    asm volatile("{ .reg .u64 g; cvta.to.global.u64 g, %1;\n\t"
        "cp.async.bulk.shared::cluster.global.mbarrier::complete_tx::bytes [%0], [g], %2, [%3]; }"
        :: "r"(dst), "l"(src), "r"(bytes), "r"(mbar) : "memory");
}

#define MB_WAIT(mb, ph) do { \
    uint32_t _m = (mb); uint32_t _p = (uint32_t)(ph); uint32_t _d; \
    asm volatile("{\n\t.reg .pred p;\n\t" \
        "mbarrier.try_wait.parity.acquire.cta.shared::cta.b64 p, [%1], %2;\n\t" \
        "selp.b32 %0, 1, 0, p;\n\t}" : "=r"(_d) : "r"(_m), "r"(_p) : "memory"); \
    if (!_d) { \
        asm volatile("{\n\t.reg .pred P1;\n\t" \
            "WAIT_LOOP_%=:\n\t" \
            "mbarrier.try_wait.parity.acquire.cta.shared::cta.b64 P1, [%0], %1, 0x989680;\n\t" \
            "@P1 bra.uni WAIT_DONE_%=;\n\t" \
            "bra.uni WAIT_LOOP_%=;\n\t" \
            "WAIT_DONE_%=:\n\t}" :: "r"(_m), "r"(_p) : "memory"); \
    } \
} while(0)

__device__ __forceinline__ void cp16(uint32_t saddr, const void* gaddr){
    asm volatile("cp.async.ca.shared.global [%0], [%1], 16;"
        :: "r"(saddr), "l"(gaddr));
}
#define CP_COMMIT() asm volatile("cp.async.commit_group;" ::: "memory")
#define CP_WAIT1()  asm volatile("cp.async.wait_group 1;" ::: "memory")
#define CP_WAIT0()  asm volatile("cp.async.wait_group 0;" ::: "memory")

__device__ __forceinline__ void ldmat4(uint32_t* r, uint32_t addr){
    asm volatile("ldmatrix.sync.aligned.m8n8.x4.shared.b16 {%0,%1,%2,%3}, [%4];"
        : "=r"(r[0]), "=r"(r[1]), "=r"(r[2]), "=r"(r[3]) : "r"(addr));
}
__device__ __forceinline__ void ldmat4t(uint32_t* r, uint32_t addr){
    asm volatile("ldmatrix.sync.aligned.m8n8.x4.trans.shared.b16 {%0,%1,%2,%3}, [%4];"
        : "=r"(r[0]), "=r"(r[1]), "=r"(r[2]), "=r"(r[3]) : "r"(addr));
}
__device__ __forceinline__ void mma16816(float* d, const uint32_t* a, const uint32_t* b){
    asm volatile("mma.sync.aligned.m16n8k16.row.col.f32.f16.f16.f32 "
        "{%0,%1,%2,%3}, {%4,%5,%6,%7}, {%8,%9}, {%0,%1,%2,%3};"
        : "+f"(d[0]), "+f"(d[1]), "+f"(d[2]), "+f"(d[3])
        : "r"(a[0]), "r"(a[1]), "r"(a[2]), "r"(a[3]), "r"(b[0]), "r"(b[1]));
}

__global__ void __launch_bounds__(256) convert_x_kernel(const float* __restrict__ xsrc)
{
    const int b = blockIdx.z, c0 = blockIdx.y * 32, p0 = blockIdx.x * 32;
    __shared__ float tile[32][33];
    const int tx = threadIdx.x & 31, ty = threadIdx.x >> 5;
    const float* s = xsrc + ((size_t)b * ND + c0) * NPIX + p0;
    #pragma unroll
    for (int i = 0; i < 32; i += 8)
        tile[ty + i][tx] = s[(size_t)(ty + i) * NPIX + tx];
    __syncthreads();
    const int cc = (threadIdx.x & 15) * 2;
    const int pr = threadIdx.x >> 4;
    #pragma unroll
    for (int pass = 0; pass < 2; pass++) {
        const int prow = pr + pass * 16;
        const int pix = p0 + prow;
        const int c = c0 + cc;
        const int chunk = c >> 6, cl = c & 63;
        size_t di = ((size_t)(b * 4 + chunk) * NPIX + pix) * 64
                  + (((cl >> 3) ^ (pix & 7)) << 3) + (cl & 7);
        *(__half2*)(g_xt2 + di) = __floats2half2_rn(tile[cc][prow], tile[cc + 1][prow]);
    }
}

__global__ void __launch_bounds__(256) convert_wqkv_kernel(
    const float* __restrict__ wq, const float* __restrict__ wk, const float* __restrict__ wv)
{
    int i = blockIdx.x * 256 + threadIdx.x;
    const float* w = (i < 65536) ? wq : (i < 131072) ? wk : wv;
    const float v = w[i & 65535];
    const int proj = i >> 16, r = i & 65535;
    const int o_g = r >> 8, c_g = r & 255;
    const int otile = o_g >> 7, o = o_g & 127, chunk = c_g >> 6, c = c_g & 63;
    const size_t pos = (size_t)(((proj * 2 + otile) * 4 + chunk)) * 8192
                     + (o << 6) + (((c >> 3) ^ (o & 7)) << 3) + (c & 7);
    g_wp2[pos] = __float2half_rn(v);
}

__global__ void __launch_bounds__(256) convert_wconv_kernel(const float* __restrict__ w_out)
{
    int i = blockIdx.x * 256 + threadIdx.x;
    const float v = w_out[i];
    const int o_g = i / 2304;
    const int rem = i - o_g * 2304;
    const int c_g = rem / 9, khw = rem - (rem / 9) * 9;
    const int otile = o_g >> 7, o = o_g & 127, chunk = c_g >> 6, c = c_g & 63;
    const size_t pos = (size_t)(((khw * 2 + otile) * 4 + chunk)) * 8192
                     + (o << 6) + (((c >> 3) ^ (o & 7)) << 3) + (c & 7);
    g_wc2[pos] = __float2half_rn(v);
}

// ---------------- QKV GEMM: B tile resident in smem, 3 projections per CTA ----------------
// smem: barriers @0; B 4x16KB @1024; A 2x16KB @66560.  Total 99328 -> 2 CTA/SM.
#define QKV_B_OFF  1024
#define QKV_A_OFF  (1024 + 65536)
#define QKV_A_SLOT 16384
#define QKV_SMEM   (1024 + 65536 + 2*QKV_A_SLOT)

__global__ void __launch_bounds__(256, 2) qkv_mma_kernel(
    const float* __restrict__ bq, const float* __restrict__ bk, const float* __restrict__ bv)
{
    extern __shared__ char smem[];
    const uint32_t sb = smem_u32(smem);
    const uint32_t bdata = sb + QKV_B_OFF;
    const uint32_t adata = sb + QKV_A_OFF;
    const int tid = threadIdx.x;
    const int lane = tid & 31, wid = tid >> 5;
    const int wm = wid >> 2, wn = wid & 3;
    const int n0 = blockIdx.x * 128;
    const int otile = blockIdx.y, o0 = otile * 128;
    const int b = blockIdx.z;

    if (tid == 0) { MB_INIT(sb, 1); MB_INIT(sb + 8, 1); MB_INIT(sb + 16, 1); }
    __syncthreads();

    auto issueA = [&](int s) {                      // s = proj*4 + chunk
        const int proj = s >> 2, ck = s & 3;
        const uint32_t mb = sb + (s & 1) * 8;
        MB_EXPECT(mb, 16384u);
        bulk_g2s(adata + (s & 1) * QKV_A_SLOT,
                 g_wp2 + (size_t)((proj * 2 + otile) * 4 + ck) * 8192, 16384u, mb);
    };
    if (tid == 0) {
        MB_EXPECT(sb + 16, 65536u);
        #pragma unroll
        for (int ck = 0; ck < 4; ck++)
            bulk_g2s(bdata + ck * 16384,
                     g_xt2 + ((size_t)(b * 4 + ck) * NPIX + n0) * 64, 16384u, sb + 16);
        issueA(0); issueA(1);
    }

    float acc[4][4][4];
    #pragma unroll
    for (int i = 0; i < 4; i++)
        #pragma unroll
        for (int j = 0; j < 4; j++)
            #pragma unroll
            for (int q = 0; q < 4; q++) acc[i][j][q] = 0.f;

    #pragma unroll 1
    for (int s = 0; s < 12; s++) {
        MB_WAIT(sb + (s & 1) * 8, (s >> 1) & 1);
        if (s == 0) MB_WAIT(sb + 16, 0);
        const uint32_t ab = adata + (s & 1) * QKV_A_SLOT;
        const uint32_t bb = bdata + (s & 3) * 16384;
        #pragma unroll
        for (int kh = 0; kh < 4; kh++) {
            uint32_t ah[4][4], bf[4][2];
            #pragma unroll
            for (int i = 0; i < 4; i++) {
                const int row = wm * 64 + i * 16 + (lane & 15);
                const int ch = (2 * kh + (lane >> 4)) ^ (row & 7);
                ldmat4(ah[i], ab + row * 128 + ch * 16);
            }
            #pragma unroll
            for (int jj = 0; jj < 2; jj++) {
                const int row = wn * 32 + jj * 16 + (lane & 7) + ((lane >> 4) << 3);
                const int ch = (2 * kh + ((lane >> 3) & 1)) ^ (row & 7);
                uint32_t r4[4];
                ldmat4(r4, bb + row * 128 + ch * 16);
                bf[2*jj][0] = r4[0]; bf[2*jj][1] = r4[1];
                bf[2*jj+1][0] = r4[2]; bf[2*jj+1][1] = r4[3];
            }
            #pragma unroll
            for (int i = 0; i < 4; i++)
                #pragma unroll
                for (int j = 0; j < 4; j++)
                    mma16816(acc[i][j], ah[i], bf[j]);
        }
        __syncthreads();
        if (tid == 0 && s + 2 < 12) issueA(s + 2);

        if ((s & 3) == 3) {
            // epilogue for this projection (R11-proven index math)
            const int proj = s >> 2;
            const float* bias = (proj == 0) ? bq : (proj == 1) ? bk : bv;
            if (proj < 2) {
                __half* qt = ((proj == 0) ? g_qt : g_kt) + (size_t)b * 64 * 16384;
                #pragma unroll
                for (int i = 0; i < 4; i++) {
                    const int r0 = o0 + wm * 64 + i * 16 + (lane >> 2);
                    const float bb0 = bias[r0], bb1 = bias[r0 + 8];
                    #pragma unroll
                    for (int j = 0; j < 4; j++) {
                        const int p = n0 + wn * 32 + j * 8 + 2 * (lane & 3);
                        const int h = p >> 6, w = p & 63;
                        const int t = ((h >> 3) << 3) + (w >> 3);
                        const int l = ((h & 7) << 3) + (w & 7);
                        __half2 v0 = __floats2half2_rn(acc[i][j][0] + bb0, acc[i][j][1] + bb0);
                        __half2 v1 = __floats2half2_rn(acc[i][j][2] + bb1, acc[i][j][3] + bb1);
                        *(__half2*)(qt + (size_t)t * 16384 + r0 * 64 + l) = v0;
                        *(__half2*)(qt + (size_t)t * 16384 + (r0 + 8) * 64 + l) = v1;
                        #pragma unroll
                        for (int q = 0; q < 4; q++) acc[i][j][q] = 0.f;
                    }
                }
            } else {
                __half* vh = g_vt  + (size_t)b * 64 * 16384;
                __half* vl = g_vtl + (size_t)b * 64 * 16384;
                #pragma unroll
                for (int i = 0; i < 4; i++) {
                    const int r0 = o0 + wm * 64 + i * 16 + (lane >> 2);
                    const float bb0 = bias[r0], bb1 = bias[r0 + 8];
                    #pragma unroll
                    for (int j = 0; j < 4; j++) {
                        const int p = n0 + wn * 32 + j * 8 + 2 * (lane & 3);
                        const int h = p >> 6, w = p & 63;
                        const int t = ((h >> 3) << 3) + (w >> 3);
                        const int l = ((h & 7) << 3) + (w & 7);
                        float f0 = acc[i][j][0] + bb0, f1 = acc[i][j][1] + bb0;
                        float f2 = acc[i][j][2] + bb1, f3 = acc[i][j][3] + bb1;
                        __half h0 = __float2half_rn(f0), h1 = __float2half_rn(f1);
                        __half h2 = __float2half_rn(f2), h3 = __float2half_rn(f3);
                        __half2 hv0; hv0.x = h0; hv0.y = h1;
                        __half2 hv1; hv1.x = h2; hv1.y = h3;
                        __half2 lv0 = __floats2half2_rn(f0 - __half2float(h0), f1 - __half2float(h1));
                        __half2 lv1 = __floats2half2_rn(f2 - __half2float(h2), f3 - __half2float(h3));
                        *(__half2*)(vh + (size_t)t * 16384 + r0 * 64 + l) = hv0;
                        *(__half2*)(vh + (size_t)t * 16384 + (r0 + 8) * 64 + l) = hv1;
                        *(__half2*)(vl + (size_t)t * 16384 + r0 * 64 + l) = lv0;
                        *(__half2*)(vl + (size_t)t * 16384 + (r0 + 8) * 64 + l) = lv1;
                    }
                }
            }
        }
    }
}

#define SC_STAGE 16384
#define SC_SMEM  (3*SC_STAGE)

__global__ void __launch_bounds__(256, 2) scores_mma_kernel()
{
    extern __shared__ char smem[];
    const uint32_t sbase = smem_u32(smem);
    const int tid = threadIdx.x;
    const int lane = tid & 31, wid = tid >> 5;
    const int wm = wid & 3, wn = wid >> 2;
    const int slice = blockIdx.x, b = blockIdx.y;
    const size_t eoff = (size_t)slice * 2048;

    const __half* Q = g_qt + (size_t)b * 64 * 16384 + eoff;
    const __half* K = g_kt + (size_t)b * 64 * 16384 + eoff;

    auto load_stage = [&](int ck, int buf) {
        const uint32_t stb = sbase + buf * SC_STAGE;
        #pragma unroll
        for (int q = 0; q < 2; q++) {
            const int idx = tid + q * 256;
            const int row = idx >> 3, c = idx & 7;
            const uint32_t so = row * 128 + ((c ^ (row & 7)) << 4);
            const size_t goff = (size_t)row * 16384 + ck * 64 + c * 8;
            cp16(stb + so,        Q + goff);
            cp16(stb + 8192 + so, K + goff);
        }
        CP_COMMIT();
    };

    float acc[4][4];
    #pragma unroll
    for (int j = 0; j < 4; j++)
        #pragma unroll
        for (int q = 0; q < 4; q++) acc[j][q] = 0.f;

    load_stage(0, 0);
    load_stage(1, 1);
    #pragma unroll 1
    for (int s = 0; s < 32; s++) {
        if (s + 1 < 32) { CP_WAIT1(); } else { CP_WAIT0(); }
        __syncthreads();
        if (s + 2 < 32) load_stage(s + 2, (s + 2) % 3);
        const uint32_t qb = sbase + (s % 3) * SC_STAGE;
        const uint32_t kb = qb + 8192;
        #pragma unroll
        for (int kh = 0; kh < 4; kh++) {
            uint32_t ah[4], bf[4][2];
            {
                const int row = wm * 16 + (lane & 15);
                const int ch = (2 * kh + (lane >> 4)) ^ (row & 7);
                ldmat4(ah, qb + row * 128 + ch * 16);
            }
            #pragma unroll
            for (int jj = 0; jj < 2; jj++) {
                const int row = wn * 32 + jj * 16 + (lane & 7) + ((lane >> 4) << 3);
                const int ch = (2 * kh + ((lane >> 3) & 1)) ^ (row & 7);
                uint32_t r4[4];
                ldmat4(r4, kb + row * 128 + ch * 16);
                bf[2*jj][0] = r4[0]; bf[2*jj][1] = r4[1];
                bf[2*jj+1][0] = r4[2]; bf[2*jj+1][1] = r4[3];
            }
            #pragma unroll
            for (int j = 0; j < 4; j++)
                mma16816(acc[j], ah, bf[j]);
        }
        __syncthreads();
    }

    float* dst = g_spart + ((size_t)(b * 8 + slice)) * 4096;
    #pragma unroll
    for (int j = 0; j < 4; j++) {
        const int r0 = wm * 16 + (lane >> 2);
        const int cb = wn * 32 + j * 8 + 2 * (lane & 3);
        *(float2*)(dst + r0 * 64 + cb)       = make_float2(acc[j][0], acc[j][1]);
        *(float2*)(dst + (r0 + 8) * 64 + cb) = make_float2(acc[j][2], acc[j][3]);
    }
}

__global__ void __launch_bounds__(64) softmax_kernel()
{
    const int b = blockIdx.x;
    const int t = threadIdx.x;
    const float scale = 1.0f / 128.0f;
    float v[64];
    #pragma unroll
    for (int u = 0; u < 64; u++) v[u] = 0.f;
    #pragma unroll 2
    for (int sl = 0; sl < 8; sl++) {
        const float* row = g_spart + ((size_t)(b * 8 + sl)) * 4096 + t * 64;
        #pragma unroll
        for (int u = 0; u < 64; u++) v[u] += row[u];
    }
    float m = -1e30f;
    #pragma unroll
    for (int u = 0; u < 64; u++) { v[u] *= scale; m = fmaxf(m, v[u]); }
    float s = 0.f;
    #pragma unroll
    for (int u = 0; u < 64; u++) { v[u] = __expf(v[u] - m); s += v[u]; }
    const float inv = 1.0f / s;
    __half* hrow = g_attn_h + b * 4096 + t * 64;
    __half* lrow = g_attn_l + b * 4096 + t * 64;
    #pragma unroll
    for (int u = 0; u < 64; u += 2) {
        float f0 = v[u] * inv, f1 = v[u+1] * inv;
        __half h0 = __float2half_rn(f0), h1 = __float2half_rn(f1);
        __half2 hh; hh.x = h0; hh.y = h1;
        *(__half2*)(hrow + u) = hh;
        *(__half2*)(lrow + u) = __floats2half2_rn(f0 - __half2float(h0), f1 - __half2float(h1));
    }
}

#define AV_AL   8192
#define AV_VH   16384
#define AV_VL   49152
#define AV_OUT  81920
#define AV_SMEM 114688

__global__ void __launch_bounds__(256, 2) av_mma_kernel()
{
    extern __shared__ char smem[];
    const uint32_t sbase = smem_u32(smem);
    const int tid = threadIdx.x;
    const int lane = tid & 31, wid = tid >> 5;
    const int wm = wid >> 1, wn = wid & 1;
    const int et = blockIdx.x, b = blockIdx.y;
    const size_t e0 = (size_t)et * 256;

    {
        const __half* Ah = g_attn_h + (size_t)b * 4096;
        const __half* Al = g_attn_l + (size_t)b * 4096;
        const __half* Vh = g_vt  + (size_t)b * 64 * 16384 + e0;
        const __half* Vl = g_vtl + (size_t)b * 64 * 16384 + e0;
        #pragma unroll
        for (int q = 0; q < 2; q++) {
            const int idx = tid + q * 256;
            const int row = idx >> 3, c = idx & 7;
            const uint32_t so = row * 128 + ((c ^ (row & 7)) << 4);
            cp16(sbase + so,         Ah + (size_t)row * 64 + c * 8);
            cp16(sbase + AV_AL + so, Al + (size_t)row * 64 + c * 8);
        }
        #pragma unroll
        for (int q = 0; q < 8; q++) {
            const int idx = tid + q * 256;
            const int row = idx >> 5, c = idx & 31;
            const int sw = (c & 24) | ((c & 7) ^ (row & 7));
            cp16(sbase + AV_VH + row * 512 + sw * 16, Vh + (size_t)row * 16384 + c * 8);
            cp16(sbase + AV_VL + row * 512 + sw * 16, Vl + (size_t)row * 16384 + c * 8);
        }
        CP_COMMIT();
        CP_WAIT0();
    }
    __syncthreads();

    float acc[16][4];
    #pragma unroll
    for (int j = 0; j < 16; j++)
        #pragma unroll
        for (int q = 0; q < 4; q++) acc[j][q] = 0.f;

    #pragma unroll
    for (int kh = 0; kh < 4; kh++) {
        uint32_t ahh[4], ahl[4];
        {
            const int row = wm * 16 + (lane & 15);
            const int ch = (2 * kh + (lane >> 4)) ^ (row & 7);
            ldmat4(ahh, sbase + row * 128 + ch * 16);
            ldmat4(ahl, sbase + AV_AL + row * 128 + ch * 16);
        }
        #pragma unroll
        for (int jj = 0; jj < 8; jj++) {
            const int u = kh * 16 + (lane & 15);
            const int c32 = wn * 16 + jj * 2 + (lane >> 4);
            const int sw = (c32 & 24) | ((c32 & 7) ^ (u & 7));
            uint32_t rh[4], rl[4];
            ldmat4t(rh, sbase + AV_VH + u * 512 + sw * 16);
            ldmat4t(rl, sbase + AV_VL + u * 512 + sw * 16);
            uint32_t bh0[2] = { rh[0], rh[1] }, bh1[2] = { rh[2], rh[3] };
            uint32_t bl0[2] = { rl[0], rl[1] }, bl1[2] = { rl[2], rl[3] };
            mma16816(acc[jj*2],   ahh, bh0);
            mma16816(acc[jj*2],   ahh, bl0);
            mma16816(acc[jj*2],   ahl, bh0);
            mma16816(acc[jj*2],   ahl, bl0);
            mma16816(acc[jj*2+1], ahh, bh1);
            mma16816(acc[jj*2+1], ahh, bl1);
            mma16816(acc[jj*2+1], ahl, bh1);
            mma16816(acc[jj*2+1], ahl, bl1);
        }
    }

    #pragma unroll
    for (int j = 0; j < 16; j++) {
        const int t0 = wm * 16 + (lane >> 2);
        const int e  = wn * 128 + j * 8 + 2 * (lane & 3);
        const int c  = e >> 3;
        const int sw0 = (c & 24) | ((c & 7) ^ (t0 & 7));
        const int sw1 = (c & 24) | ((c & 7) ^ ((t0 + 8) & 7));
        __half2 v0 = __floats2half2_rn(acc[j][0], acc[j][1]);
        __half2 v1 = __floats2half2_rn(acc[j][2], acc[j][3]);
        *(__half2*)(smem + AV_OUT + t0 * 512 + sw0 * 16 + (e & 7) * 2) = v0;
        *(__half2*)(smem + AV_OUT + (t0 + 8) * 512 + sw1 * 16 + (e & 7) * 2) = v1;
    }
    __syncthreads();

    const int d0g = et * 4;
    const int chunk_g = d0g >> 6, cl0 = d0g & 63;
    __half* outg = g_aot2 + ((size_t)(b * 4 + chunk_g)) * NPIX * 64;
    #pragma unroll
    for (int p = 0; p < 16; p++) {
        const int pix = tid + p * 256;
        const int h = pix >> 6, w = pix & 63;
        const int t = ((h >> 3) << 3) + (w >> 3);
        const int l = ((h & 7) << 3) + (w & 7);
        uint32_t hv[4];
        #pragma unroll
        for (int dq = 0; dq < 4; dq++) {
            const int sw = dq * 8 + ((l >> 3) ^ (t & 7));
            hv[dq] = *(const uint16_t*)(smem + AV_OUT + t * 512 + sw * 16 + (l & 7) * 2);
        }
        uint2 pk;
        pk.x = hv[0] | (hv[1] << 16);
        pk.y = hv[2] | (hv[3] << 16);
        const size_t off = (size_t)pix * 64 + (((cl0 >> 3) ^ (pix & 7)) << 3) + (cl0 & 7);
        *(uint2*)(outg + off) = pk;
    }
}

#define CV_A_SLOT  16384
#define CV_HALO    (1024 + 3*CV_A_SLOT)
#define CV_SMEM    (CV_HALO + 33792)

__global__ void __launch_bounds__(128, 2) conv_mma_kernel(
    const float* __restrict__ b_out, const float* __restrict__ gamma,
    const float* __restrict__ beta,  const float* __restrict__ bn_mean,
    const float* __restrict__ bn_var, float* __restrict__ out)
{
    extern __shared__ char smem[];
    const uint32_t sb = smem_u32(smem);
    const uint32_t data = sb + 1024;
    const uint32_t halo = sb + CV_HALO;
    const int tid = threadIdx.x;
    const int lane = tid & 31, wid = tid >> 5;
    const int wm = wid >> 1, wn = wid & 1;
    const int pt = blockIdx.x;
    const int otile = blockIdx.y, o0 = otile * 128;
    const int b = blockIdx.z;
    const int h0 = pt * 2, n0 = pt * 128;

    const __half* Bbase = g_aot2 + (size_t)(b * 4) * NPIX * 64;

    if (tid == 0) { MB_INIT(sb, 1); MB_INIT(sb + 8, 1); MB_INIT(sb + 16, 1); MB_INIT(sb + 24, 1); }
    {
        const int4 z = make_int4(0, 0, 0, 0);
        for (int idx = tid; idx < 2112; idx += 128)
            *(int4*)(smem + CV_HALO + idx * 16) = z;
    }
    __syncthreads();

    auto issueA = [&](int s) {
        const int khw = s % 9, chunk = s / 9;
        const uint32_t mb = sb + (s % 3) * 8;
        MB_EXPECT(mb, 16384u);
        bulk_g2s(data + (s % 3) * CV_A_SLOT,
                 g_wc2 + (size_t)((khw * 2 + otile) * 4 + chunk) * 8192, 16384u, mb);
    };
    auto issueHalo = [&](int chunk) {
        const uint32_t mb = sb + 24;
        uint32_t bytes = 0;
        #pragma unroll
        for (int hr = 0; hr < 4; hr++) {
            const int h2 = h0 - 1 + hr;
            if ((unsigned)h2 < 64u) bytes += 8192u;
        }
        MB_EXPECT(mb, bytes);
        #pragma unroll
        for (int hr = 0; hr < 4; hr++) {
            const int h2 = h0 - 1 + hr;
            if ((unsigned)h2 < 64u)
                bulk_g2s(halo + hr * 8448 + 128,
                         Bbase + ((size_t)chunk * NPIX + h2 * 64) * 64, 8192u, mb);
        }
    };
    if (tid == 0) { issueHalo(0); issueA(0); issueA(1); issueA(2); }

    float acc[4][8][4];
    #pragma unroll
    for (int i = 0; i < 4; i++)
        #pragma unroll
        for (int j = 0; j < 8; j++)
            #pragma unroll
            for (int q = 0; q < 4; q++) acc[i][j][q] = 0.f;

    #pragma unroll 1
    for (int s = 0; s < 36; s++) {
        const int khw = s % 9, chunk = s / 9;
        MB_WAIT(sb + (s % 3) * 8, (s / 3) & 1);
        if (khw == 0) MB_WAIT(sb + 24, chunk & 1);
        const int dh = khw / 3 - 1, dw = khw % 3 - 1;
        const uint32_t ab = data + (s % 3) * CV_A_SLOT;
        #pragma unroll
        for (int kh = 0; kh < 4; kh++) {
            uint32_t ah[4][4], bf[8][2];
            #pragma unroll
            for (int i = 0; i < 4; i++) {
                const int row = wm * 64 + i * 16 + (lane & 15);
                const int ch = (2 * kh + (lane >> 4)) ^ (row & 7);
                ldmat4(ah[i], ab + row * 128 + ch * 16);
            }
            #pragma unroll
            for (int jj = 0; jj < 4; jj++) {
                const int p = wn * 64 + jj * 16 + (lane & 7) + ((lane >> 4) << 3);
                const int w2 = (p & 63) + dw;
                const int er = (p >> 6) + dh + 1;
                const int e = er * 66 + w2 + 1;
                const int ch = (2 * kh + ((lane >> 3) & 1)) ^ (w2 & 7);
                uint32_t r4[4];
                ldmat4(r4, halo + e * 128 + ch * 16);
                bf[2*jj][0] = r4[0]; bf[2*jj][1] = r4[1];
                bf[2*jj+1][0] = r4[2]; bf[2*jj+1][1] = r4[3];
            }
            #pragma unroll
            for (int i = 0; i < 4; i++)
                #pragma unroll
                for (int j = 0; j < 8; j++)
                    mma16816(acc[i][j], ah[i], bf[j]);
        }
        __syncthreads();
        if (tid == 0) {
            if (s + 3 < 36) issueA(s + 3);
            if (khw == 8 && chunk < 3) issueHalo(chunk + 1);
        }
    }

    float* dst = out + (size_t)b * ND * NPIX;
    #pragma unroll
    for (int i = 0; i < 4; i++) {
        const int r0 = o0 + wm * 64 + i * 16 + (lane >> 2);
        const float sc0 = gamma[r0]     * rsqrtf(bn_var[r0]     + 1e-5f);
        const float sc1 = gamma[r0 + 8] * rsqrtf(bn_var[r0 + 8] + 1e-5f);
        const float ad0 = (b_out[r0]     - bn_mean[r0])     * sc0 + beta[r0];
        const float ad1 = (b_out[r0 + 8] - bn_mean[r0 + 8]) * sc1 + beta[r0 + 8];
        #pragma unroll
        for (int j = 0; j < 8; j++) {
            const int cb = n0 + wn * 64 + j * 8 + 2 * (lane & 3);
            float t0 = acc[i][j][0] * sc0 + ad0;
            float t1 = acc[i][j][1] * sc0 + ad0;
            float t2 = acc[i][j][2] * sc1 + ad1;
            float t3 = acc[i][j][3] * sc1 + ad1;
            float2 v0 = make_float2((t0 >= 0.f) ? t0 : 0.2f * t0,
                                    (t1 >= 0.f) ? t1 : 0.2f * t1);
            float2 v1 = make_float2((t2 >= 0.f) ? t2 : 0.2f * t2,
                                    (t3 >= 0.f) ? t3 : 0.2f * t3);
            *(float2*)(dst + (size_t)r0 * NPIX + cb) = v0;
            *(float2*)(dst + (size_t)(r0 + 8) * NPIX + cb) = v1;
        }
    }
}

extern "C" void kernel_launch(void* const* d_in, const int* in_sizes, int n_in,
                              void* d_out, int out_size)
{
    const float* x       = (const float*)d_in[0];
    const float* wq      = (const float*)d_in[1];
    const float* bq      = (const float*)d_in[2];
    const float* wk      = (const float*)d_in[3];
    const float* bk      = (const float*)d_in[4];
    const float* wv      = (const float*)d_in[5];
    const float* bv      = (const float*)d_in[6];
    const float* w_out   = (const float*)d_in[7];
    const float* b_out   = (const float*)d_in[8];
    const float* gamma   = (const float*)d_in[9];
    const float* beta    = (const float*)d_in[10];
    const float* bn_mean = (const float*)d_in[11];
    const float* bn_var  = (const float*)d_in[12];
    float* out = (float*)d_out;

    cudaFuncSetAttribute(qkv_mma_kernel,    cudaFuncAttributeMaxDynamicSharedMemorySize, QKV_SMEM);
    cudaFuncSetAttribute(scores_mma_kernel, cudaFuncAttributeMaxDynamicSharedMemorySize, SC_SMEM);
    cudaFuncSetAttribute(av_mma_kernel,     cudaFuncAttributeMaxDynamicSharedMemorySize, AV_SMEM);
    cudaFuncSetAttribute(conv_mma_kernel,   cudaFuncAttributeMaxDynamicSharedMemorySize, CV_SMEM);

    convert_wqkv_kernel <<<768,  256>>>(wq, wk, wv);
    convert_wconv_kernel<<<2304, 256>>>(w_out);
    convert_x_kernel<<<dim3(128, 8, 16), 256>>>(x);

    qkv_mma_kernel<<<dim3(32, 2, 16), 256, QKV_SMEM>>>(bq, bk, bv);

    scores_mma_kernel<<<dim3(8, 16), 256, SC_SMEM>>>();
    softmax_kernel<<<16, 64>>>();
    av_mma_kernel<<<dim3(64, 16), 256, AV_SMEM>>>();

    conv_mma_kernel<<<dim3(32, 2, 16), 128, CV_SMEM>>>(b_out, gamma, beta, bn_mean, bn_var, out);
}

// round 15
// speedup vs baseline: 1.0475x; 1.0080x over previous
#include <cuda_runtime.h>
#include <cuda_fp16.h>
#include <cstdint>
#include <math.h>

#define NB 16
#define ND 256
#define NPIX 4096

__device__ float g_spart[NB*8*64*64];
__device__ __align__(16) __half g_attn_h[NB*64*64];
__device__ __align__(16) __half g_attn_l[NB*64*64];

// token-major, e = o*64 + l  (o = channel, l = in-patch position)
__device__ __align__(16) __half g_qt [NB*64*16384];
__device__ __align__(16) __half g_kt [NB*64*16384];
__device__ __align__(16) __half g_vt [NB*64*16384];
__device__ __align__(16) __half g_vtl[NB*64*16384];
__device__ __align__(16) __half g_xt2 [NB*4*NPIX*64];
__device__ __align__(16) __half g_aot2[NB*4*NPIX*64];
__device__ __align__(16) __half g_wp2 [3*2*4*128*64];
__device__ __align__(16) __half g_wc2 [9*2*4*128*64];

__device__ __forceinline__ uint32_t smem_u32(const void* p){
    uint32_t a;
    asm("{ .reg .u64 t; cvta.to.shared.u64 t, %1; cvt.u32.u64 %0, t; }" : "=r"(a) : "l"(p));
    return a;
}
#define MB_INIT(mb, n) asm volatile("mbarrier.init.shared.b64 [%0], %1;" :: "r"(mb), "r"(n) : "memory")
#define MB_EXPECT(mb, bytes) asm volatile("mbarrier.arrive.expect_tx.shared.b64 _, [%0], %1;" :: "r"(mb), "r"(bytes) : "memory")

__device__ __forceinline__ void bulk_g2s(uint32_t dst, const void* src, uint32_t bytes, uint32_t mbar){
    asm volatile("{ .reg .u64 g; cvta.to.global.u64 g, %1;\n\t"
        "cp.async.bulk.shared::cluster.global.mbarrier::complete_tx::bytes [%0], [g], %2, [%3]; }"
        :: "r"(dst), "l"(src), "r"(bytes), "r"(mbar) : "memory");
}

#define MB_WAIT(mb, ph) do { \
    uint32_t _m = (mb); uint32_t _p = (uint32_t)(ph); uint32_t _d; \
    asm volatile("{\n\t.reg .pred p;\n\t" \
        "mbarrier.try_wait.parity.acquire.cta.shared::cta.b64 p, [%1], %2;\n\t" \
        "selp.b32 %0, 1, 0, p;\n\t}" : "=r"(_d) : "r"(_m), "r"(_p) : "memory"); \
    if (!_d) { \
        asm volatile("{\n\t.reg .pred P1;\n\t" \
            "WAIT_LOOP_%=:\n\t" \
            "mbarrier.try_wait.parity.acquire.cta.shared::cta.b64 P1, [%0], %1, 0x989680;\n\t" \
            "@P1 bra.uni WAIT_DONE_%=;\n\t" \
            "bra.uni WAIT_LOOP_%=;\n\t" \
            "WAIT_DONE_%=:\n\t}" :: "r"(_m), "r"(_p) : "memory"); \
    } \
} while(0)

__device__ __forceinline__ void cp16(uint32_t saddr, const void* gaddr){
    asm volatile("cp.async.ca.shared.global [%0], [%1], 16;"
        :: "r"(saddr), "l"(gaddr));
}
#define CP_COMMIT() asm volatile("cp.async.commit_group;" ::: "memory")
#define CP_WAIT1()  asm volatile("cp.async.wait_group 1;" ::: "memory")
#define CP_WAIT0()  asm volatile("cp.async.wait_group 0;" ::: "memory")

__device__ __forceinline__ void ldmat4(uint32_t* r, uint32_t addr){
    asm volatile("ldmatrix.sync.aligned.m8n8.x4.shared.b16 {%0,%1,%2,%3}, [%4];"
        : "=r"(r[0]), "=r"(r[1]), "=r"(r[2]), "=r"(r[3]) : "r"(addr));
}
__device__ __forceinline__ void ldmat4t(uint32_t* r, uint32_t addr){
    asm volatile("ldmatrix.sync.aligned.m8n8.x4.trans.shared.b16 {%0,%1,%2,%3}, [%4];"
        : "=r"(r[0]), "=r"(r[1]), "=r"(r[2]), "=r"(r[3]) : "r"(addr));
}
__device__ __forceinline__ void mma16816(float* d, const uint32_t* a, const uint32_t* b){
    asm volatile("mma.sync.aligned.m16n8k16.row.col.f32.f16.f16.f32 "
        "{%0,%1,%2,%3}, {%4,%5,%6,%7}, {%8,%9}, {%0,%1,%2,%3};"
        : "+f"(d[0]), "+f"(d[1]), "+f"(d[2]), "+f"(d[3])
        : "r"(a[0]), "r"(a[1]), "r"(a[2]), "r"(a[3]), "r"(b[0]), "r"(b[1]));
}

__global__ void __launch_bounds__(256) convert_x_kernel(const float* __restrict__ xsrc)
{
    const int b = blockIdx.z, c0 = blockIdx.y * 32, p0 = blockIdx.x * 32;
    __shared__ float tile[32][33];
    const int tx = threadIdx.x & 31, ty = threadIdx.x >> 5;
    const float* s = xsrc + ((size_t)b * ND + c0) * NPIX + p0;
    #pragma unroll
    for (int i = 0; i < 32; i += 8)
        tile[ty + i][tx] = s[(size_t)(ty + i) * NPIX + tx];
    __syncthreads();
    const int cc = (threadIdx.x & 15) * 2;
    const int pr = threadIdx.x >> 4;
    #pragma unroll
    for (int pass = 0; pass < 2; pass++) {
        const int prow = pr + pass * 16;
        const int pix = p0 + prow;
        const int c = c0 + cc;
        const int chunk = c >> 6, cl = c & 63;
        size_t di = ((size_t)(b * 4 + chunk) * NPIX + pix) * 64
                  + (((cl >> 3) ^ (pix & 7)) << 3) + (cl & 7);
        *(__half2*)(g_xt2 + di) = __floats2half2_rn(tile[cc][prow], tile[cc + 1][prow]);
    }
}

__global__ void __launch_bounds__(256) convert_wqkv_kernel(
    const float* __restrict__ wq, const float* __restrict__ wk, const float* __restrict__ wv)
{
    int i = blockIdx.x * 256 + threadIdx.x;
    const float* w = (i < 65536) ? wq : (i < 131072) ? wk : wv;
    const float v = w[i & 65535];
    const int proj = i >> 16, r = i & 65535;
    const int o_g = r >> 8, c_g = r & 255;
    const int otile = o_g >> 7, o = o_g & 127, chunk = c_g >> 6, c = c_g & 63;
    const size_t pos = (size_t)(((proj * 2 + otile) * 4 + chunk)) * 8192
                     + (o << 6) + (((c >> 3) ^ (o & 7)) << 3) + (c & 7);
    g_wp2[pos] = __float2half_rn(v);
}

__global__ void __launch_bounds__(256) convert_wconv_kernel(const float* __restrict__ w_out)
{
    int i = blockIdx.x * 256 + threadIdx.x;
    const float v = w_out[i];
    const int o_g = i / 2304;
    const int rem = i - o_g * 2304;
    const int c_g = rem / 9, khw = rem - (rem / 9) * 9;
    const int otile = o_g >> 7, o = o_g & 127, chunk = c_g >> 6, c = c_g & 63;
    const size_t pos = (size_t)(((khw * 2 + otile) * 4 + chunk)) * 8192
                     + (o << 6) + (((c >> 3) ^ (o & 7)) << 3) + (c & 7);
    g_wc2[pos] = __float2half_rn(v);
}

// ---------------- QKV GEMM: 128 thr, 64x64 warp tiles, resident B, 3 proj/CTA ----------------
#define QKV_B_OFF  1024
#define QKV_A_OFF  (1024 + 65536)
#define QKV_A_SLOT 16384
#define QKV_SMEM   (1024 + 65536 + 2*QKV_A_SLOT)

__global__ void __launch_bounds__(128, 2) qkv_mma_kernel(
    const float* __restrict__ bq, const float* __restrict__ bk, const float* __restrict__ bv)
{
    extern __shared__ char smem[];
    const uint32_t sb = smem_u32(smem);
    const uint32_t bdata = sb + QKV_B_OFF;
    const uint32_t adata = sb + QKV_A_OFF;
    const int tid = threadIdx.x;
    const int lane = tid & 31, wid = tid >> 5;   // 4 warps
    const int wm = wid >> 1, wn = wid & 1;       // warp tile: o64 x pix64
    const int n0 = blockIdx.x * 128;
    const int otile = blockIdx.y, o0 = otile * 128;
    const int b = blockIdx.z;

    if (tid == 0) { MB_INIT(sb, 1); MB_INIT(sb + 8, 1); MB_INIT(sb + 16, 1); }
    __syncthreads();

    auto issueA = [&](int s) {                   // s = proj*4 + chunk
        const int proj = s >> 2, ck = s & 3;
        const uint32_t mb = sb + (s & 1) * 8;
        MB_EXPECT(mb, 16384u);
        bulk_g2s(adata + (s & 1) * QKV_A_SLOT,
                 g_wp2 + (size_t)((proj * 2 + otile) * 4 + ck) * 8192, 16384u, mb);
    };
    if (tid == 0) {
        MB_EXPECT(sb + 16, 65536u);
        #pragma unroll
        for (int ck = 0; ck < 4; ck++)
            bulk_g2s(bdata + ck * 16384,
                     g_xt2 + ((size_t)(b * 4 + ck) * NPIX + n0) * 64, 16384u, sb + 16);
        issueA(0); issueA(1);
    }

    float acc[4][8][4];
    #pragma unroll
    for (int i = 0; i < 4; i++)
        #pragma unroll
        for (int j = 0; j < 8; j++)
            #pragma unroll
            for (int q = 0; q < 4; q++) acc[i][j][q] = 0.f;

    #pragma unroll 1
    for (int s = 0; s < 12; s++) {
        MB_WAIT(sb + (s & 1) * 8, (s >> 1) & 1);
        if (s == 0) MB_WAIT(sb + 16, 0);
        const uint32_t ab = adata + (s & 1) * QKV_A_SLOT;
        const uint32_t bb = bdata + (s & 3) * 16384;
        #pragma unroll
        for (int kh = 0; kh < 4; kh++) {
            uint32_t ah[4][4], bf[8][2];
            #pragma unroll
            for (int i = 0; i < 4; i++) {
                const int row = wm * 64 + i * 16 + (lane & 15);
                const int ch = (2 * kh + (lane >> 4)) ^ (row & 7);
                ldmat4(ah[i], ab + row * 128 + ch * 16);
            }
            #pragma unroll
            for (int jj = 0; jj < 4; jj++) {
                const int row = wn * 64 + jj * 16 + (lane & 7) + ((lane >> 4) << 3);
                const int ch = (2 * kh + ((lane >> 3) & 1)) ^ (row & 7);
                uint32_t r4[4];
                ldmat4(r4, bb + row * 128 + ch * 16);
                bf[2*jj][0] = r4[0]; bf[2*jj][1] = r4[1];
                bf[2*jj+1][0] = r4[2]; bf[2*jj+1][1] = r4[3];
            }
            #pragma unroll
            for (int i = 0; i < 4; i++)
                #pragma unroll
                for (int j = 0; j < 8; j++)
                    mma16816(acc[i][j], ah[i], bf[j]);
        }
        __syncthreads();
        if (tid == 0 && s + 2 < 12) issueA(s + 2);

        if ((s & 3) == 3) {
            const int proj = s >> 2;
            const float* bias = (proj == 0) ? bq : (proj == 1) ? bk : bv;
            if (proj < 2) {
                __half* qt = ((proj == 0) ? g_qt : g_kt) + (size_t)b * 64 * 16384;
                #pragma unroll
                for (int i = 0; i < 4; i++) {
                    const int r0 = o0 + wm * 64 + i * 16 + (lane >> 2);
                    const float bb0 = bias[r0], bb1 = bias[r0 + 8];
                    #pragma unroll
                    for (int j = 0; j < 8; j++) {
                        const int p = n0 + wn * 64 + j * 8 + 2 * (lane & 3);
                        const int h = p >> 6, w = p & 63;
                        const int t = ((h >> 3) << 3) + (w >> 3);
                        const int l = ((h & 7) << 3) + (w & 7);
                        __half2 v0 = __floats2half2_rn(acc[i][j][0] + bb0, acc[i][j][1] + bb0);
                        __half2 v1 = __floats2half2_rn(acc[i][j][2] + bb1, acc[i][j][3] + bb1);
                        *(__half2*)(qt + (size_t)t * 16384 + r0 * 64 + l) = v0;
                        *(__half2*)(qt + (size_t)t * 16384 + (r0 + 8) * 64 + l) = v1;
                        #pragma unroll
                        for (int q = 0; q < 4; q++) acc[i][j][q] = 0.f;
                    }
                }
            } else {
                __half* vh = g_vt  + (size_t)b * 64 * 16384;
                __half* vl = g_vtl + (size_t)b * 64 * 16384;
                #pragma unroll
                for (int i = 0; i < 4; i++) {
                    const int r0 = o0 + wm * 64 + i * 16 + (lane >> 2);
                    const float bb0 = bias[r0], bb1 = bias[r0 + 8];
                    #pragma unroll
                    for (int j = 0; j < 8; j++) {
                        const int p = n0 + wn * 64 + j * 8 + 2 * (lane & 3);
                        const int h = p >> 6, w = p & 63;
                        const int t = ((h >> 3) << 3) + (w >> 3);
                        const int l = ((h & 7) << 3) + (w & 7);
                        float f0 = acc[i][j][0] + bb0, f1 = acc[i][j][1] + bb0;
                        float f2 = acc[i][j][2] + bb1, f3 = acc[i][j][3] + bb1;
                        __half h0 = __float2half_rn(f0), h1 = __float2half_rn(f1);
                        __half h2 = __float2half_rn(f2), h3 = __float2half_rn(f3);
                        __half2 hv0; hv0.x = h0; hv0.y = h1;
                        __half2 hv1; hv1.x = h2; hv1.y = h3;
                        __half2 lv0 = __floats2half2_rn(f0 - __half2float(h0), f1 - __half2float(h1));
                        __half2 lv1 = __floats2half2_rn(f2 - __half2float(h2), f3 - __half2float(h3));
                        *(__half2*)(vh + (size_t)t * 16384 + r0 * 64 + l) = hv0;
                        *(__half2*)(vh + (size_t)t * 16384 + (r0 + 8) * 64 + l) = hv1;
                        *(__half2*)(vl + (size_t)t * 16384 + r0 * 64 + l) = lv0;
                        *(__half2*)(vl + (size_t)t * 16384 + (r0 + 8) * 64 + l) = lv1;
                    }
                }
            }
        }
    }
}

#define SC_STAGE 16384
#define SC_SMEM  (3*SC_STAGE)

__global__ void __launch_bounds__(256, 2) scores_mma_kernel()
{
    extern __shared__ char smem[];
    const uint32_t sbase = smem_u32(smem);
    const int tid = threadIdx.x;
    const int lane = tid & 31, wid = tid >> 5;
    const int wm = wid & 3, wn = wid >> 2;
    const int slice = blockIdx.x, b = blockIdx.y;
    const size_t eoff = (size_t)slice * 2048;

    const __half* Q = g_qt + (size_t)b * 64 * 16384 + eoff;
    const __half* K = g_kt + (size_t)b * 64 * 16384 + eoff;

    auto load_stage = [&](int ck, int buf) {
        const uint32_t stb = sbase + buf * SC_STAGE;
        #pragma unroll
        for (int q = 0; q < 2; q++) {
            const int idx = tid + q * 256;
            const int row = idx >> 3, c = idx & 7;
            const uint32_t so = row * 128 + ((c ^ (row & 7)) << 4);
            const size_t goff = (size_t)row * 16384 + ck * 64 + c * 8;
            cp16(stb + so,        Q + goff);
            cp16(stb + 8192 + so, K + goff);
        }
        CP_COMMIT();
    };

    float acc[4][4];
    #pragma unroll
    for (int j = 0; j < 4; j++)
        #pragma unroll
        for (int q = 0; q < 4; q++) acc[j][q] = 0.f;

    load_stage(0, 0);
    load_stage(1, 1);
    #pragma unroll 1
    for (int s = 0; s < 32; s++) {
        if (s + 1 < 32) { CP_WAIT1(); } else { CP_WAIT0(); }
        __syncthreads();
        if (s + 2 < 32) load_stage(s + 2, (s + 2) % 3);
        const uint32_t qb = sbase + (s % 3) * SC_STAGE;
        const uint32_t kb = qb + 8192;
        #pragma unroll
        for (int kh = 0; kh < 4; kh++) {
            uint32_t ah[4], bf[4][2];
            {
                const int row = wm * 16 + (lane & 15);
                const int ch = (2 * kh + (lane >> 4)) ^ (row & 7);
                ldmat4(ah, qb + row * 128 + ch * 16);
            }
            #pragma unroll
            for (int jj = 0; jj < 2; jj++) {
                const int row = wn * 32 + jj * 16 + (lane & 7) + ((lane >> 4) << 3);
                const int ch = (2 * kh + ((lane >> 3) & 1)) ^ (row & 7);
                uint32_t r4[4];
                ldmat4(r4, kb + row * 128 + ch * 16);
                bf[2*jj][0] = r4[0]; bf[2*jj][1] = r4[1];
                bf[2*jj+1][0] = r4[2]; bf[2*jj+1][1] = r4[3];
            }
            #pragma unroll
            for (int j = 0; j < 4; j++)
                mma16816(acc[j], ah, bf[j]);
        }
        __syncthreads();
    }

    float* dst = g_spart + ((size_t)(b * 8 + slice)) * 4096;
    #pragma unroll
    for (int j = 0; j < 4; j++) {
        const int r0 = wm * 16 + (lane >> 2);
        const int cb = wn * 32 + j * 8 + 2 * (lane & 3);
        *(float2*)(dst + r0 * 64 + cb)       = make_float2(acc[j][0], acc[j][1]);
        *(float2*)(dst + (r0 + 8) * 64 + cb) = make_float2(acc[j][2], acc[j][3]);
    }
}

__global__ void __launch_bounds__(64) softmax_kernel()
{
    const int b = blockIdx.x;
    const int t = threadIdx.x;
    const float scale = 1.0f / 128.0f;
    float v[64];
    #pragma unroll
    for (int u = 0; u < 64; u++) v[u] = 0.f;
    #pragma unroll 2
    for (int sl = 0; sl < 8; sl++) {
        const float* row = g_spart + ((size_t)(b * 8 + sl)) * 4096 + t * 64;
        #pragma unroll
        for (int u = 0; u < 64; u++) v[u] += row[u];
    }
    float m = -1e30f;
    #pragma unroll
    for (int u = 0; u < 64; u++) { v[u] *= scale; m = fmaxf(m, v[u]); }
    float s = 0.f;
    #pragma unroll
    for (int u = 0; u < 64; u++) { v[u] = __expf(v[u] - m); s += v[u]; }
    const float inv = 1.0f / s;
    __half* hrow = g_attn_h + b * 4096 + t * 64;
    __half* lrow = g_attn_l + b * 4096 + t * 64;
    #pragma unroll
    for (int u = 0; u < 64; u += 2) {
        float f0 = v[u] * inv, f1 = v[u+1] * inv;
        __half h0 = __float2half_rn(f0), h1 = __float2half_rn(f1);
        __half2 hh; hh.x = h0; hh.y = h1;
        *(__half2*)(hrow + u) = hh;
        *(__half2*)(lrow + u) = __floats2half2_rn(f0 - __half2float(h0), f1 - __half2float(h1));
    }
}

#define AV_AL   8192
#define AV_VH   16384
#define AV_VL   49152
#define AV_OUT  81920
#define AV_SMEM 114688

__global__ void __launch_bounds__(256, 2) av_mma_kernel()
{
    extern __shared__ char smem[];
    const uint32_t sbase = smem_u32(smem);
    const int tid = threadIdx.x;
    const int lane = tid & 31, wid = tid >> 5;
    const int wm = wid >> 1, wn = wid & 1;
    const int et = blockIdx.x, b = blockIdx.y;
    const size_t e0 = (size_t)et * 256;

    {
        const __half* Ah = g_attn_h + (size_t)b * 4096;
        const __half* Al = g_attn_l + (size_t)b * 4096;
        const __half* Vh = g_vt  + (size_t)b * 64 * 16384 + e0;
        const __half* Vl = g_vtl + (size_t)b * 64 * 16384 + e0;
        #pragma unroll
        for (int q = 0; q < 2; q++) {
            const int idx = tid + q * 256;
            const int row = idx >> 3, c = idx & 7;
            const uint32_t so = row * 128 + ((c ^ (row & 7)) << 4);
            cp16(sbase + so,         Ah + (size_t)row * 64 + c * 8);
            cp16(sbase + AV_AL + so, Al + (size_t)row * 64 + c * 8);
        }
        #pragma unroll
        for (int q = 0; q < 8; q++) {
            const int idx = tid + q * 256;
            const int row = idx >> 5, c = idx & 31;
            const int sw = (c & 24) | ((c & 7) ^ (row & 7));
            cp16(sbase + AV_VH + row * 512 + sw * 16, Vh + (size_t)row * 16384 + c * 8);
            cp16(sbase + AV_VL + row * 512 + sw * 16, Vl + (size_t)row * 16384 + c * 8);
        }
        CP_COMMIT();
        CP_WAIT0();
    }
    __syncthreads();

    float acc[16][4];
    #pragma unroll
    for (int j = 0; j < 16; j++)
        #pragma unroll
        for (int q = 0; q < 4; q++) acc[j][q] = 0.f;

    #pragma unroll
    for (int kh = 0; kh < 4; kh++) {
        uint32_t ahh[4], ahl[4];
        {
            const int row = wm * 16 + (lane & 15);
            const int ch = (2 * kh + (lane >> 4)) ^ (row & 7);
            ldmat4(ahh, sbase + row * 128 + ch * 16);
            ldmat4(ahl, sbase + AV_AL + row * 128 + ch * 16);
        }
        #pragma unroll
        for (int jj = 0; jj < 8; jj++) {
            const int u = kh * 16 + (lane & 15);
            const int c32 = wn * 16 + jj * 2 + (lane >> 4);
            const int sw = (c32 & 24) | ((c32 & 7) ^ (u & 7));
            uint32_t rh[4], rl[4];
            ldmat4t(rh, sbase + AV_VH + u * 512 + sw * 16);
            ldmat4t(rl, sbase + AV_VL + u * 512 + sw * 16);
            uint32_t bh0[2] = { rh[0], rh[1] }, bh1[2] = { rh[2], rh[3] };
            uint32_t bl0[2] = { rl[0], rl[1] }, bl1[2] = { rl[2], rl[3] };
            mma16816(acc[jj*2],   ahh, bh0);
            mma16816(acc[jj*2],   ahh, bl0);
            mma16816(acc[jj*2],   ahl, bh0);
            mma16816(acc[jj*2],   ahl, bl0);
            mma16816(acc[jj*2+1], ahh, bh1);
            mma16816(acc[jj*2+1], ahh, bl1);
            mma16816(acc[jj*2+1], ahl, bh1);
            mma16816(acc[jj*2+1], ahl, bl1);
        }
    }

    #pragma unroll
    for (int j = 0; j < 16; j++) {
        const int t0 = wm * 16 + (lane >> 2);
        const int e  = wn * 128 + j * 8 + 2 * (lane & 3);
        const int c  = e >> 3;
        const int sw0 = (c & 24) | ((c & 7) ^ (t0 & 7));
        const int sw1 = (c & 24) | ((c & 7) ^ ((t0 + 8) & 7));
        __half2 v0 = __floats2half2_rn(acc[j][0], acc[j][1]);
        __half2 v1 = __floats2half2_rn(acc[j][2], acc[j][3]);
        *(__half2*)(smem + AV_OUT + t0 * 512 + sw0 * 16 + (e & 7) * 2) = v0;
        *(__half2*)(smem + AV_OUT + (t0 + 8) * 512 + sw1 * 16 + (e & 7) * 2) = v1;
    }
    __syncthreads();

    const int d0g = et * 4;
    const int chunk_g = d0g >> 6, cl0 = d0g & 63;
    __half* outg = g_aot2 + ((size_t)(b * 4 + chunk_g)) * NPIX * 64;
    #pragma unroll
    for (int p = 0; p < 16; p++) {
        const int pix = tid + p * 256;
        const int h = pix >> 6, w = pix & 63;
        const int t = ((h >> 3) << 3) + (w >> 3);
        const int l = ((h & 7) << 3) + (w & 7);
        uint32_t hv[4];
        #pragma unroll
        for (int dq = 0; dq < 4; dq++) {
            const int sw = dq * 8 + ((l >> 3) ^ (t & 7));
            hv[dq] = *(const uint16_t*)(smem + AV_OUT + t * 512 + sw * 16 + (l & 7) * 2);
        }
        uint2 pk;
        pk.x = hv[0] | (hv[1] << 16);
        pk.y = hv[2] | (hv[3] << 16);
        const size_t off = (size_t)pix * 64 + (((cl0 >> 3) ^ (pix & 7)) << 3) + (cl0 & 7);
        *(uint2*)(outg + off) = pk;
    }
}

#define CV_A_SLOT  16384
#define CV_HALO    (1024 + 3*CV_A_SLOT)
#define CV_SMEM    (CV_HALO + 33792)

__global__ void __launch_bounds__(128, 2) conv_mma_kernel(
    const float* __restrict__ b_out, const float* __restrict__ gamma,
    const float* __restrict__ beta,  const float* __restrict__ bn_mean,
    const float* __restrict__ bn_var, float* __restrict__ out)
{
    extern __shared__ char smem[];
    const uint32_t sb = smem_u32(smem);
    const uint32_t data = sb + 1024;
    const uint32_t halo = sb + CV_HALO;
    const int tid = threadIdx.x;
    const int lane = tid & 31, wid = tid >> 5;
    const int wm = wid >> 1, wn = wid & 1;
    const int pt = blockIdx.x;
    const int otile = blockIdx.y, o0 = otile * 128;
    const int b = blockIdx.z;
    const int h0 = pt * 2, n0 = pt * 128;

    const __half* Bbase = g_aot2 + (size_t)(b * 4) * NPIX * 64;

    if (tid == 0) { MB_INIT(sb, 1); MB_INIT(sb + 8, 1); MB_INIT(sb + 16, 1); MB_INIT(sb + 24, 1); }
    {
        const int4 z = make_int4(0, 0, 0, 0);
        for (int idx = tid; idx < 2112; idx += 128)
            *(int4*)(smem + CV_HALO + idx * 16) = z;
    }
    __syncthreads();

    auto issueA = [&](int s) {
        const int khw = s % 9, chunk = s / 9;
        const uint32_t mb = sb + (s % 3) * 8;
        MB_EXPECT(mb, 16384u);
        bulk_g2s(data + (s % 3) * CV_A_SLOT,
                 g_wc2 + (size_t)((khw * 2 + otile) * 4 + chunk) * 8192, 16384u, mb);
    };
    auto issueHalo = [&](int chunk) {
        const uint32_t mb = sb + 24;
        uint32_t bytes = 0;
        #pragma unroll
        for (int hr = 0; hr < 4; hr++) {
            const int h2 = h0 - 1 + hr;
            if ((unsigned)h2 < 64u) bytes += 8192u;
        }
        MB_EXPECT(mb, bytes);
        #pragma unroll
        for (int hr = 0; hr < 4; hr++) {
            const int h2 = h0 - 1 + hr;
            if ((unsigned)h2 < 64u)
                bulk_g2s(halo + hr * 8448 + 128,
                         Bbase + ((size_t)chunk * NPIX + h2 * 64) * 64, 8192u, mb);
        }
    };
    if (tid == 0) { issueHalo(0); issueA(0); issueA(1); issueA(2); }

    float acc[4][8][4];
    #pragma unroll
    for (int i = 0; i < 4; i++)
        #pragma unroll
        for (int j = 0; j < 8; j++)
            #pragma unroll
            for (int q = 0; q < 4; q++) acc[i][j][q] = 0.f;

    #pragma unroll 1
    for (int s = 0; s < 36; s++) {
        const int khw = s % 9, chunk = s / 9;
        MB_WAIT(sb + (s % 3) * 8, (s / 3) & 1);
        if (khw == 0) MB_WAIT(sb + 24, chunk & 1);
        const int dh = khw / 3 - 1, dw = khw % 3 - 1;
        const uint32_t ab = data + (s % 3) * CV_A_SLOT;
        #pragma unroll
        for (int kh = 0; kh < 4; kh++) {
            uint32_t ah[4][4], bf[8][2];
            #pragma unroll
            for (int i = 0; i < 4; i++) {
                const int row = wm * 64 + i * 16 + (lane & 15);
                const int ch = (2 * kh + (lane >> 4)) ^ (row & 7);
                ldmat4(ah[i], ab + row * 128 + ch * 16);
            }
            #pragma unroll
            for (int jj = 0; jj < 4; jj++) {
                const int p = wn * 64 + jj * 16 + (lane & 7) + ((lane >> 4) << 3);
                const int w2 = (p & 63) + dw;
                const int er = (p >> 6) + dh + 1;
                const int e = er * 66 + w2 + 1;
                const int ch = (2 * kh + ((lane >> 3) & 1)) ^ (w2 & 7);
                uint32_t r4[4];
                ldmat4(r4, halo + e * 128 + ch * 16);
                bf[2*jj][0] = r4[0]; bf[2*jj][1] = r4[1];
                bf[2*jj+1][0] = r4[2]; bf[2*jj+1][1] = r4[3];
            }
            #pragma unroll
            for (int i = 0; i < 4; i++)
                #pragma unroll
                for (int j = 0; j < 8; j++)
                    mma16816(acc[i][j], ah[i], bf[j]);
        }
        __syncthreads();
        if (tid == 0) {
            if (s + 3 < 36) issueA(s + 3);
            if (khw == 8 && chunk < 3) issueHalo(chunk + 1);
        }
    }

    float* dst = out + (size_t)b * ND * NPIX;
    #pragma unroll
    for (int i = 0; i < 4; i++) {
        const int r0 = o0 + wm * 64 + i * 16 + (lane >> 2);
        const float sc0 = gamma[r0]     * rsqrtf(bn_var[r0]     + 1e-5f);
        const float sc1 = gamma[r0 + 8] * rsqrtf(bn_var[r0 + 8] + 1e-5f);
        const float ad0 = (b_out[r0]     - bn_mean[r0])     * sc0 + beta[r0];
        const float ad1 = (b_out[r0 + 8] - bn_mean[r0 + 8]) * sc1 + beta[r0 + 8];
        #pragma unroll
        for (int j = 0; j < 8; j++) {
            const int cb = n0 + wn * 64 + j * 8 + 2 * (lane & 3);
            float t0 = acc[i][j][0] * sc0 + ad0;
            float t1 = acc[i][j][1] * sc0 + ad0;
            float t2 = acc[i][j][2] * sc1 + ad1;
            float t3 = acc[i][j][3] * sc1 + ad1;
            float2 v0 = make_float2((t0 >= 0.f) ? t0 : 0.2f * t0,
                                    (t1 >= 0.f) ? t1 : 0.2f * t1);
            float2 v1 = make_float2((t2 >= 0.f) ? t2 : 0.2f * t2,
                                    (t3 >= 0.f) ? t3 : 0.2f * t3);
            *(float2*)(dst + (size_t)r0 * NPIX + cb) = v0;
            *(float2*)(dst + (size_t)(r0 + 8) * NPIX + cb) = v1;
        }
    }
}

extern "C" void kernel_launch(void* const* d_in, const int* in_sizes, int n_in,
                              void* d_out, int out_size)
{
    const float* x       = (const float*)d_in[0];
    const float* wq      = (const float*)d_in[1];
    const float* bq      = (const float*)d_in[2];
    const float* wk      = (const float*)d_in[3];
    const float* bk      = (const float*)d_in[4];
    const float* wv      = (const float*)d_in[5];
    const float* bv      = (const float*)d_in[6];
    const float* w_out   = (const float*)d_in[7];
    const float* b_out   = (const float*)d_in[8];
    const float* gamma   = (const float*)d_in[9];
    const float* beta    = (const float*)d_in[10];
    const float* bn_mean = (const float*)d_in[11];
    const float* bn_var  = (const float*)d_in[12];
    float* out = (float*)d_out;

    cudaFuncSetAttribute(qkv_mma_kernel,    cudaFuncAttributeMaxDynamicSharedMemorySize, QKV_SMEM);
    cudaFuncSetAttribute(scores_mma_kernel, cudaFuncAttributeMaxDynamicSharedMemorySize, SC_SMEM);
    cudaFuncSetAttribute(av_mma_kernel,     cudaFuncAttributeMaxDynamicSharedMemorySize, AV_SMEM);
    cudaFuncSetAttribute(conv_mma_kernel,   cudaFuncAttributeMaxDynamicSharedMemorySize, CV_SMEM);

    convert_wqkv_kernel <<<768,  256>>>(wq, wk, wv);
    convert_wconv_kernel<<<2304, 256>>>(w_out);
    convert_x_kernel<<<dim3(128, 8, 16), 256>>>(x);

    qkv_mma_kernel<<<dim3(32, 2, 16), 128, QKV_SMEM>>>(bq, bk, bv);

    scores_mma_kernel<<<dim3(8, 16), 256, SC_SMEM>>>();
    softmax_kernel<<<16, 64>>>();
    av_mma_kernel<<<dim3(64, 16), 256, AV_SMEM>>>();

    conv_mma_kernel<<<dim3(32, 2, 16), 128, CV_SMEM>>>(b_out, gamma, beta, bn_mean, bn_var, out);
}

// round 16
// speedup vs baseline: 1.1211x; 1.0702x over previous
#include <cuda_runtime.h>
#include <cuda_fp16.h>
#include <cstdint>
#include <math.h>

#define NB 16
#define ND 256
#define NPIX 4096

__device__ float g_spart[NB*16*64*64];
__device__ __align__(16) __half g_attn_h[NB*64*64];
__device__ __align__(16) __half g_attn_l[NB*64*64];

// token-major, e = o*64 + l  (o = channel, l = in-patch position)
__device__ __align__(16) __half g_qt [NB*64*16384];
__device__ __align__(16) __half g_kt [NB*64*16384];
__device__ __align__(16) __half g_vt [NB*64*16384];
__device__ __align__(16) __half g_vtl[NB*64*16384];
__device__ __align__(16) __half g_xt2 [NB*4*NPIX*64];
__device__ __align__(16) __half g_aot2[NB*4*NPIX*64];
__device__ __align__(16) __half g_wp2 [3*2*4*128*64];
__device__ __align__(16) __half g_wc2 [9*2*4*128*64];

__device__ __forceinline__ uint32_t smem_u32(const void* p){
    uint32_t a;
    asm("{ .reg .u64 t; cvta.to.shared.u64 t, %1; cvt.u32.u64 %0, t; }" : "=r"(a) : "l"(p));
    return a;
}
#define MB_INIT(mb, n) asm volatile("mbarrier.init.shared.b64 [%0], %1;" :: "r"(mb), "r"(n) : "memory")
#define MB_EXPECT(mb, bytes) asm volatile("mbarrier.arrive.expect_tx.shared.b64 _, [%0], %1;" :: "r"(mb), "r"(bytes) : "memory")

__device__ __forceinline__ void bulk_g2s(uint32_t dst, const void* src, uint32_t bytes, uint32_t mbar){
    asm volatile("{ .reg .u64 g; cvta.to.global.u64 g, %1;\n\t"
        "cp.async.bulk.shared::cluster.global.mbarrier::complete_tx::bytes [%0], [g], %2, [%3]; }"
        :: "r"(dst), "l"(src), "r"(bytes), "r"(mbar) : "memory");
}

#define MB_WAIT(mb, ph) do { \
    uint32_t _m = (mb); uint32_t _p = (uint32_t)(ph); uint32_t _d; \
    asm volatile("{\n\t.reg .pred p;\n\t" \
        "mbarrier.try_wait.parity.acquire.cta.shared::cta.b64 p, [%1], %2;\n\t" \
        "selp.b32 %0, 1, 0, p;\n\t}" : "=r"(_d) : "r"(_m), "r"(_p) : "memory"); \
    if (!_d) { \
        asm volatile("{\n\t.reg .pred P1;\n\t" \
            "WAIT_LOOP_%=:\n\t" \
            "mbarrier.try_wait.parity.acquire.cta.shared::cta.b64 P1, [%0], %1, 0x989680;\n\t" \
            "@P1 bra.uni WAIT_DONE_%=;\n\t" \
            "bra.uni WAIT_LOOP_%=;\n\t" \
            "WAIT_DONE_%=:\n\t}" :: "r"(_m), "r"(_p) : "memory"); \
    } \
} while(0)

__device__ __forceinline__ void cp16(uint32_t saddr, const void* gaddr){
    asm volatile("cp.async.ca.shared.global [%0], [%1], 16;"
        :: "r"(saddr), "l"(gaddr));
}
#define CP_COMMIT() asm volatile("cp.async.commit_group;" ::: "memory")
#define CP_WAIT1()  asm volatile("cp.async.wait_group 1;" ::: "memory")
#define CP_WAIT0()  asm volatile("cp.async.wait_group 0;" ::: "memory")

__device__ __forceinline__ void ldmat4(uint32_t* r, uint32_t addr){
    asm volatile("ldmatrix.sync.aligned.m8n8.x4.shared.b16 {%0,%1,%2,%3}, [%4];"
        : "=r"(r[0]), "=r"(r[1]), "=r"(r[2]), "=r"(r[3]) : "r"(addr));
}
__device__ __forceinline__ void ldmat4t(uint32_t* r, uint32_t addr){
    asm volatile("ldmatrix.sync.aligned.m8n8.x4.trans.shared.b16 {%0,%1,%2,%3}, [%4];"
        : "=r"(r[0]), "=r"(r[1]), "=r"(r[2]), "=r"(r[3]) : "r"(addr));
}
__device__ __forceinline__ void mma16816(float* d, const uint32_t* a, const uint32_t* b){
    asm volatile("mma.sync.aligned.m16n8k16.row.col.f32.f16.f16.f32 "
        "{%0,%1,%2,%3}, {%4,%5,%6,%7}, {%8,%9}, {%0,%1,%2,%3};"
        : "+f"(d[0]), "+f"(d[1]), "+f"(d[2]), "+f"(d[3])
        : "r"(a[0]), "r"(a[1]), "r"(a[2]), "r"(a[3]), "r"(b[0]), "r"(b[1]));
}

__global__ void __launch_bounds__(256) convert_x_kernel(const float* __restrict__ xsrc)
{
    const int b = blockIdx.z, c0 = blockIdx.y * 32, p0 = blockIdx.x * 32;
    __shared__ float tile[32][33];
    const int tx = threadIdx.x & 31, ty = threadIdx.x >> 5;
    const float* s = xsrc + ((size_t)b * ND + c0) * NPIX + p0;
    #pragma unroll
    for (int i = 0; i < 32; i += 8)
        tile[ty + i][tx] = s[(size_t)(ty + i) * NPIX + tx];
    __syncthreads();
    const int cc = (threadIdx.x & 15) * 2;
    const int pr = threadIdx.x >> 4;
    #pragma unroll
    for (int pass = 0; pass < 2; pass++) {
        const int prow = pr + pass * 16;
        const int pix = p0 + prow;
        const int c = c0 + cc;
        const int chunk = c >> 6, cl = c & 63;
        size_t di = ((size_t)(b * 4 + chunk) * NPIX + pix) * 64
                  + (((cl >> 3) ^ (pix & 7)) << 3) + (cl & 7);
        *(__half2*)(g_xt2 + di) = __floats2half2_rn(tile[cc][prow], tile[cc + 1][prow]);
    }
}

__global__ void __launch_bounds__(256) convert_wqkv_kernel(
    const float* __restrict__ wq, const float* __restrict__ wk, const float* __restrict__ wv)
{
    int i = blockIdx.x * 256 + threadIdx.x;
    const float* w = (i < 65536) ? wq : (i < 131072) ? wk : wv;
    const float v = w[i & 65535];
    const int proj = i >> 16, r = i & 65535;
    const int o_g = r >> 8, c_g = r & 255;
    const int otile = o_g >> 7, o = o_g & 127, chunk = c_g >> 6, c = c_g & 63;
    const size_t pos = (size_t)(((proj * 2 + otile) * 4 + chunk)) * 8192
                     + (o << 6) + (((c >> 3) ^ (o & 7)) << 3) + (c & 7);
    g_wp2[pos] = __float2half_rn(v);
}

__global__ void __launch_bounds__(256) convert_wconv_kernel(const float* __restrict__ w_out)
{
    int i = blockIdx.x * 256 + threadIdx.x;
    const float v = w_out[i];
    const int o_g = i / 2304;
    const int rem = i - o_g * 2304;
    const int c_g = rem / 9, khw = rem - (rem / 9) * 9;
    const int otile = o_g >> 7, o = o_g & 127, chunk = c_g >> 6, c = c_g & 63;
    const size_t pos = (size_t)(((khw * 2 + otile) * 4 + chunk)) * 8192
                     + (o << 6) + (((c >> 3) ^ (o & 7)) << 3) + (c & 7);
    g_wc2[pos] = __float2half_rn(v);
}

// ---------------- QKV GEMM: 128 thr, 64x64 warp tiles, resident B, 3 proj/CTA ----------------
#define QKV_B_OFF  1024
#define QKV_A_OFF  (1024 + 65536)
#define QKV_A_SLOT 16384
#define QKV_SMEM   (1024 + 65536 + 2*QKV_A_SLOT)

__global__ void __launch_bounds__(128, 2) qkv_mma_kernel(
    const float* __restrict__ bq, const float* __restrict__ bk, const float* __restrict__ bv)
{
    extern __shared__ char smem[];
    const uint32_t sb = smem_u32(smem);
    const uint32_t bdata = sb + QKV_B_OFF;
    const uint32_t adata = sb + QKV_A_OFF;
    const int tid = threadIdx.x;
    const int lane = tid & 31, wid = tid >> 5;
    const int wm = wid >> 1, wn = wid & 1;
    const int n0 = blockIdx.x * 128;
    const int otile = blockIdx.y, o0 = otile * 128;
    const int b = blockIdx.z;

    if (tid == 0) { MB_INIT(sb, 1); MB_INIT(sb + 8, 1); MB_INIT(sb + 16, 1); }
    __syncthreads();

    auto issueA = [&](int s) {
        const int proj = s >> 2, ck = s & 3;
        const uint32_t mb = sb + (s & 1) * 8;
        MB_EXPECT(mb, 16384u);
        bulk_g2s(adata + (s & 1) * QKV_A_SLOT,
                 g_wp2 + (size_t)((proj * 2 + otile) * 4 + ck) * 8192, 16384u, mb);
    };
    if (tid == 0) {
        MB_EXPECT(sb + 16, 65536u);
        #pragma unroll
        for (int ck = 0; ck < 4; ck++)
            bulk_g2s(bdata + ck * 16384,
                     g_xt2 + ((size_t)(b * 4 + ck) * NPIX + n0) * 64, 16384u, sb + 16);
        issueA(0); issueA(1);
    }

    float acc[4][8][4];
    #pragma unroll
    for (int i = 0; i < 4; i++)
        #pragma unroll
        for (int j = 0; j < 8; j++)
            #pragma unroll
            for (int q = 0; q < 4; q++) acc[i][j][q] = 0.f;

    #pragma unroll 1
    for (int s = 0; s < 12; s++) {
        MB_WAIT(sb + (s & 1) * 8, (s >> 1) & 1);
        if (s == 0) MB_WAIT(sb + 16, 0);
        const uint32_t ab = adata + (s & 1) * QKV_A_SLOT;
        const uint32_t bb = bdata + (s & 3) * 16384;
        #pragma unroll
        for (int kh = 0; kh < 4; kh++) {
            uint32_t ah[4][4], bf[8][2];
            #pragma unroll
            for (int i = 0; i < 4; i++) {
                const int row = wm * 64 + i * 16 + (lane & 15);
                const int ch = (2 * kh + (lane >> 4)) ^ (row & 7);
                ldmat4(ah[i], ab + row * 128 + ch * 16);
            }
            #pragma unroll
            for (int jj = 0; jj < 4; jj++) {
                const int row = wn * 64 + jj * 16 + (lane & 7) + ((lane >> 4) << 3);
                const int ch = (2 * kh + ((lane >> 3) & 1)) ^ (row & 7);
                uint32_t r4[4];
                ldmat4(r4, bb + row * 128 + ch * 16);
                bf[2*jj][0] = r4[0]; bf[2*jj][1] = r4[1];
                bf[2*jj+1][0] = r4[2]; bf[2*jj+1][1] = r4[3];
            }
            #pragma unroll
            for (int i = 0; i < 4; i++)
                #pragma unroll
                for (int j = 0; j < 8; j++)
                    mma16816(acc[i][j], ah[i], bf[j]);
        }
        __syncthreads();
        if (tid == 0 && s + 2 < 12) issueA(s + 2);

        if ((s & 3) == 3) {
            const int proj = s >> 2;
            const float* bias = (proj == 0) ? bq : (proj == 1) ? bk : bv;
            if (proj < 2) {
                __half* qt = ((proj == 0) ? g_qt : g_kt) + (size_t)b * 64 * 16384;
                #pragma unroll
                for (int i = 0; i < 4; i++) {
                    const int r0 = o0 + wm * 64 + i * 16 + (lane >> 2);
                    const float bb0 = bias[r0], bb1 = bias[r0 + 8];
                    #pragma unroll
                    for (int j = 0; j < 8; j++) {
                        const int p = n0 + wn * 64 + j * 8 + 2 * (lane & 3);
                        const int h = p >> 6, w = p & 63;
                        const int t = ((h >> 3) << 3) + (w >> 3);
                        const int l = ((h & 7) << 3) + (w & 7);
                        __half2 v0 = __floats2half2_rn(acc[i][j][0] + bb0, acc[i][j][1] + bb0);
                        __half2 v1 = __floats2half2_rn(acc[i][j][2] + bb1, acc[i][j][3] + bb1);
                        *(__half2*)(qt + (size_t)t * 16384 + r0 * 64 + l) = v0;
                        *(__half2*)(qt + (size_t)t * 16384 + (r0 + 8) * 64 + l) = v1;
                        #pragma unroll
                        for (int q = 0; q < 4; q++) acc[i][j][q] = 0.f;
                    }
                }
            } else {
                __half* vh = g_vt  + (size_t)b * 64 * 16384;
                __half* vl = g_vtl + (size_t)b * 64 * 16384;
                #pragma unroll
                for (int i = 0; i < 4; i++) {
                    const int r0 = o0 + wm * 64 + i * 16 + (lane >> 2);
                    const float bb0 = bias[r0], bb1 = bias[r0 + 8];
                    #pragma unroll
                    for (int j = 0; j < 8; j++) {
                        const int p = n0 + wn * 64 + j * 8 + 2 * (lane & 3);
                        const int h = p >> 6, w = p & 63;
                        const int t = ((h >> 3) << 3) + (w >> 3);
                        const int l = ((h & 7) << 3) + (w & 7);
                        float f0 = acc[i][j][0] + bb0, f1 = acc[i][j][1] + bb0;
                        float f2 = acc[i][j][2] + bb1, f3 = acc[i][j][3] + bb1;
                        __half h0 = __float2half_rn(f0), h1 = __float2half_rn(f1);
                        __half h2 = __float2half_rn(f2), h3 = __float2half_rn(f3);
                        __half2 hv0; hv0.x = h0; hv0.y = h1;
                        __half2 hv1; hv1.x = h2; hv1.y = h3;
                        __half2 lv0 = __floats2half2_rn(f0 - __half2float(h0), f1 - __half2float(h1));
                        __half2 lv1 = __floats2half2_rn(f2 - __half2float(h2), f3 - __half2float(h3));
                        *(__half2*)(vh + (size_t)t * 16384 + r0 * 64 + l) = hv0;
                        *(__half2*)(vh + (size_t)t * 16384 + (r0 + 8) * 64 + l) = hv1;
                        *(__half2*)(vl + (size_t)t * 16384 + r0 * 64 + l) = lv0;
                        *(__half2*)(vl + (size_t)t * 16384 + (r0 + 8) * 64 + l) = lv1;
                    }
                }
            }
        }
    }
}

// ---------------- scores via mma: 16 e-slices of 1024 ----------------
#define SC_STAGE 16384
#define SC_SMEM  (3*SC_STAGE)

__global__ void __launch_bounds__(256, 2) scores_mma_kernel()
{
    extern __shared__ char smem[];
    const uint32_t sbase = smem_u32(smem);
    const int tid = threadIdx.x;
    const int lane = tid & 31, wid = tid >> 5;
    const int wm = wid & 3, wn = wid >> 2;
    const int slice = blockIdx.x, b = blockIdx.y;
    const size_t eoff = (size_t)slice * 1024;

    const __half* Q = g_qt + (size_t)b * 64 * 16384 + eoff;
    const __half* K = g_kt + (size_t)b * 64 * 16384 + eoff;

    auto load_stage = [&](int ck, int buf) {
        const uint32_t stb = sbase + buf * SC_STAGE;
        #pragma unroll
        for (int q = 0; q < 2; q++) {
            const int idx = tid + q * 256;
            const int row = idx >> 3, c = idx & 7;
            const uint32_t so = row * 128 + ((c ^ (row & 7)) << 4);
            const size_t goff = (size_t)row * 16384 + ck * 64 + c * 8;
            cp16(stb + so,        Q + goff);
            cp16(stb + 8192 + so, K + goff);
        }
        CP_COMMIT();
    };

    float acc[4][4];
    #pragma unroll
    for (int j = 0; j < 4; j++)
        #pragma unroll
        for (int q = 0; q < 4; q++) acc[j][q] = 0.f;

    load_stage(0, 0);
    load_stage(1, 1);
    #pragma unroll 1
    for (int s = 0; s < 16; s++) {
        if (s + 1 < 16) { CP_WAIT1(); } else { CP_WAIT0(); }
        __syncthreads();
        if (s + 2 < 16) load_stage(s + 2, (s + 2) % 3);
        const uint32_t qb = sbase + (s % 3) * SC_STAGE;
        const uint32_t kb = qb + 8192;
        #pragma unroll
        for (int kh = 0; kh < 4; kh++) {
            uint32_t ah[4], bf[4][2];
            {
                const int row = wm * 16 + (lane & 15);
                const int ch = (2 * kh + (lane >> 4)) ^ (row & 7);
                ldmat4(ah, qb + row * 128 + ch * 16);
            }
            #pragma unroll
            for (int jj = 0; jj < 2; jj++) {
                const int row = wn * 32 + jj * 16 + (lane & 7) + ((lane >> 4) << 3);
                const int ch = (2 * kh + ((lane >> 3) & 1)) ^ (row & 7);
                uint32_t r4[4];
                ldmat4(r4, kb + row * 128 + ch * 16);
                bf[2*jj][0] = r4[0]; bf[2*jj][1] = r4[1];
                bf[2*jj+1][0] = r4[2]; bf[2*jj+1][1] = r4[3];
            }
            #pragma unroll
            for (int j = 0; j < 4; j++)
                mma16816(acc[j], ah, bf[j]);
        }
        __syncthreads();
    }

    float* dst = g_spart + ((size_t)(b * 16 + slice)) * 4096;
    #pragma unroll
    for (int j = 0; j < 4; j++) {
        const int r0 = wm * 16 + (lane >> 2);
        const int cb = wn * 32 + j * 8 + 2 * (lane & 3);
        *(float2*)(dst + r0 * 64 + cb)       = make_float2(acc[j][0], acc[j][1]);
        *(float2*)(dst + (r0 + 8) * 64 + cb) = make_float2(acc[j][2], acc[j][3]);
    }
}

// ---------------- softmax: warp-per-row ----------------
__global__ void __launch_bounds__(256) softmax_kernel()
{
    const int g = blockIdx.x * 8 + (threadIdx.x >> 5);   // global row 0..1023
    const int lane = threadIdx.x & 31;
    const int b = g >> 6, t = g & 63;
    const int c0 = lane * 2;
    const float scale = 1.0f / 128.0f;

    float v0 = 0.f, v1 = 0.f;
    const float* base = g_spart + (size_t)(b * 16) * 4096 + t * 64 + c0;
    #pragma unroll
    for (int sl = 0; sl < 16; sl++) {
        const float2 p = *(const float2*)(base + (size_t)sl * 4096);
        v0 += p.x; v1 += p.y;
    }
    v0 *= scale; v1 *= scale;
    float m = fmaxf(v0, v1);
    #pragma unroll
    for (int o = 16; o > 0; o >>= 1)
        m = fmaxf(m, __shfl_xor_sync(0xffffffffu, m, o));
    v0 = __expf(v0 - m); v1 = __expf(v1 - m);
    float s = v0 + v1;
    #pragma unroll
    for (int o = 16; o > 0; o >>= 1)
        s += __shfl_xor_sync(0xffffffffu, s, o);
    const float inv = 1.0f / s;
    const float f0 = v0 * inv, f1 = v1 * inv;
    const __half h0 = __float2half_rn(f0), h1 = __float2half_rn(f1);
    __half2 hh; hh.x = h0; hh.y = h1;
    *(__half2*)(g_attn_h + b * 4096 + t * 64 + c0) = hh;
    *(__half2*)(g_attn_l + b * 4096 + t * 64 + c0) =
        __floats2half2_rn(f0 - __half2float(h0), f1 - __half2float(h1));
}

#define AV_AL   8192
#define AV_VH   16384
#define AV_VL   49152
#define AV_OUT  81920
#define AV_SMEM 114688

__global__ void __launch_bounds__(256, 2) av_mma_kernel()
{
    extern __shared__ char smem[];
    const uint32_t sbase = smem_u32(smem);
    const int tid = threadIdx.x;
    const int lane = tid & 31, wid = tid >> 5;
    const int wm = wid >> 1, wn = wid & 1;
    const int et = blockIdx.x, b = blockIdx.y;
    const size_t e0 = (size_t)et * 256;

    {
        const __half* Ah = g_attn_h + (size_t)b * 4096;
        const __half* Al = g_attn_l + (size_t)b * 4096;
        const __half* Vh = g_vt  + (size_t)b * 64 * 16384 + e0;
        const __half* Vl = g_vtl + (size_t)b * 64 * 16384 + e0;
        #pragma unroll
        for (int q = 0; q < 2; q++) {
            const int idx = tid + q * 256;
            const int row = idx >> 3, c = idx & 7;
            const uint32_t so = row * 128 + ((c ^ (row & 7)) << 4);
            cp16(sbase + so,         Ah + (size_t)row * 64 + c * 8);
            cp16(sbase + AV_AL + so, Al + (size_t)row * 64 + c * 8);
        }
        #pragma unroll
        for (int q = 0; q < 8; q++) {
            const int idx = tid + q * 256;
            const int row = idx >> 5, c = idx & 31;
            const int sw = (c & 24) | ((c & 7) ^ (row & 7));
            cp16(sbase + AV_VH + row * 512 + sw * 16, Vh + (size_t)row * 16384 + c * 8);
            cp16(sbase + AV_VL + row * 512 + sw * 16, Vl + (size_t)row * 16384 + c * 8);
        }
        CP_COMMIT();
        CP_WAIT0();
    }
    __syncthreads();

    float acc[16][4];
    #pragma unroll
    for (int j = 0; j < 16; j++)
        #pragma unroll
        for (int q = 0; q < 4; q++) acc[j][q] = 0.f;

    #pragma unroll
    for (int kh = 0; kh < 4; kh++) {
        uint32_t ahh[4], ahl[4];
        {
            const int row = wm * 16 + (lane & 15);
            const int ch = (2 * kh + (lane >> 4)) ^ (row & 7);
            ldmat4(ahh, sbase + row * 128 + ch * 16);
            ldmat4(ahl, sbase + AV_AL + row * 128 + ch * 16);
        }
        #pragma unroll
        for (int jj = 0; jj < 8; jj++) {
            const int u = kh * 16 + (lane & 15);
            const int c32 = wn * 16 + jj * 2 + (lane >> 4);
            const int sw = (c32 & 24) | ((c32 & 7) ^ (u & 7));
            uint32_t rh[4], rl[4];
            ldmat4t(rh, sbase + AV_VH + u * 512 + sw * 16);
            ldmat4t(rl, sbase + AV_VL + u * 512 + sw * 16);
            uint32_t bh0[2] = { rh[0], rh[1] }, bh1[2] = { rh[2], rh[3] };
            uint32_t bl0[2] = { rl[0], rl[1] }, bl1[2] = { rl[2], rl[3] };
            mma16816(acc[jj*2],   ahh, bh0);
            mma16816(acc[jj*2],   ahh, bl0);
            mma16816(acc[jj*2],   ahl, bh0);
            mma16816(acc[jj*2],   ahl, bl0);
            mma16816(acc[jj*2+1], ahh, bh1);
            mma16816(acc[jj*2+1], ahh, bl1);
            mma16816(acc[jj*2+1], ahl, bh1);
            mma16816(acc[jj*2+1], ahl, bl1);
        }
    }

    #pragma unroll
    for (int j = 0; j < 16; j++) {
        const int t0 = wm * 16 + (lane >> 2);
        const int e  = wn * 128 + j * 8 + 2 * (lane & 3);
        const int c  = e >> 3;
        const int sw0 = (c & 24) | ((c & 7) ^ (t0 & 7));
        const int sw1 = (c & 24) | ((c & 7) ^ ((t0 + 8) & 7));
        __half2 v0 = __floats2half2_rn(acc[j][0], acc[j][1]);
        __half2 v1 = __floats2half2_rn(acc[j][2], acc[j][3]);
        *(__half2*)(smem + AV_OUT + t0 * 512 + sw0 * 16 + (e & 7) * 2) = v0;
        *(__half2*)(smem + AV_OUT + (t0 + 8) * 512 + sw1 * 16 + (e & 7) * 2) = v1;
    }
    __syncthreads();

    const int d0g = et * 4;
    const int chunk_g = d0g >> 6, cl0 = d0g & 63;
    __half* outg = g_aot2 + ((size_t)(b * 4 + chunk_g)) * NPIX * 64;
    #pragma unroll
    for (int p = 0; p < 16; p++) {
        const int pix = tid + p * 256;
        const int h = pix >> 6, w = pix & 63;
        const int t = ((h >> 3) << 3) + (w >> 3);
        const int l = ((h & 7) << 3) + (w & 7);
        uint32_t hv[4];
        #pragma unroll
        for (int dq = 0; dq < 4; dq++) {
            const int sw = dq * 8 + ((l >> 3) ^ (t & 7));
            hv[dq] = *(const uint16_t*)(smem + AV_OUT + t * 512 + sw * 16 + (l & 7) * 2);
        }
        uint2 pk;
        pk.x = hv[0] | (hv[1] << 16);
        pk.y = hv[2] | (hv[3] << 16);
        const size_t off = (size_t)pix * 64 + (((cl0 >> 3) ^ (pix & 7)) << 3) + (cl0 & 7);
        *(uint2*)(outg + off) = pk;
    }
}

#define CV_A_SLOT  16384
#define CV_HALO    (1024 + 3*CV_A_SLOT)
#define CV_SMEM    (CV_HALO + 33792)

__global__ void __launch_bounds__(128, 2) conv_mma_kernel(
    const float* __restrict__ b_out, const float* __restrict__ gamma,
    const float* __restrict__ beta,  const float* __restrict__ bn_mean,
    const float* __restrict__ bn_var, float* __restrict__ out)
{
    extern __shared__ char smem[];
    const uint32_t sb = smem_u32(smem);
    const uint32_t data = sb + 1024;
    const uint32_t halo = sb + CV_HALO;
    const int tid = threadIdx.x;
    const int lane = tid & 31, wid = tid >> 5;
    const int wm = wid >> 1, wn = wid & 1;
    const int pt = blockIdx.x;
    const int otile = blockIdx.y, o0 = otile * 128;
    const int b = blockIdx.z;
    const int h0 = pt * 2, n0 = pt * 128;

    const __half* Bbase = g_aot2 + (size_t)(b * 4) * NPIX * 64;

    if (tid == 0) { MB_INIT(sb, 1); MB_INIT(sb + 8, 1); MB_INIT(sb + 16, 1); MB_INIT(sb + 24, 1); }
    {
        const int4 z = make_int4(0, 0, 0, 0);
        for (int idx = tid; idx < 2112; idx += 128)
            *(int4*)(smem + CV_HALO + idx * 16) = z;
    }
    __syncthreads();

    auto issueA = [&](int s) {
        const int khw = s % 9, chunk = s / 9;
        const uint32_t mb = sb + (s % 3) * 8;
        MB_EXPECT(mb, 16384u);
        bulk_g2s(data + (s % 3) * CV_A_SLOT,
                 g_wc2 + (size_t)((khw * 2 + otile) * 4 + chunk) * 8192, 16384u, mb);
    };
    auto issueHalo = [&](int chunk) {
        const uint32_t mb = sb + 24;
        uint32_t bytes = 0;
        #pragma unroll
        for (int hr = 0; hr < 4; hr++) {
            const int h2 = h0 - 1 + hr;
            if ((unsigned)h2 < 64u) bytes += 8192u;
        }
        MB_EXPECT(mb, bytes);
        #pragma unroll
        for (int hr = 0; hr < 4; hr++) {
            const int h2 = h0 - 1 + hr;
            if ((unsigned)h2 < 64u)
                bulk_g2s(halo + hr * 8448 + 128,
                         Bbase + ((size_t)chunk * NPIX + h2 * 64) * 64, 8192u, mb);
        }
    };
    if (tid == 0) { issueHalo(0); issueA(0); issueA(1); issueA(2); }

    float acc[4][8][4];
    #pragma unroll
    for (int i = 0; i < 4; i++)
        #pragma unroll
        for (int j = 0; j < 8; j++)
            #pragma unroll
            for (int q = 0; q < 4; q++) acc[i][j][q] = 0.f;

    #pragma unroll 1
    for (int s = 0; s < 36; s++) {
        const int khw = s % 9, chunk = s / 9;
        MB_WAIT(sb + (s % 3) * 8, (s / 3) & 1);
        if (khw == 0) MB_WAIT(sb + 24, chunk & 1);
        const int dh = khw / 3 - 1, dw = khw % 3 - 1;
        const uint32_t ab = data + (s % 3) * CV_A_SLOT;
        #pragma unroll
        for (int kh = 0; kh < 4; kh++) {
            uint32_t ah[4][4], bf[8][2];
            #pragma unroll
            for (int i = 0; i < 4; i++) {
                const int row = wm * 64 + i * 16 + (lane & 15);
                const int ch = (2 * kh + (lane >> 4)) ^ (row & 7);
                ldmat4(ah[i], ab + row * 128 + ch * 16);
            }
            #pragma unroll
            for (int jj = 0; jj < 4; jj++) {
                const int p = wn * 64 + jj * 16 + (lane & 7) + ((lane >> 4) << 3);
                const int w2 = (p & 63) + dw;
                const int er = (p >> 6) + dh + 1;
                const int e = er * 66 + w2 + 1;
                const int ch = (2 * kh + ((lane >> 3) & 1)) ^ (w2 & 7);
                uint32_t r4[4];
                ldmat4(r4, halo + e * 128 + ch * 16);
                bf[2*jj][0] = r4[0]; bf[2*jj][1] = r4[1];
                bf[2*jj+1][0] = r4[2]; bf[2*jj+1][1] = r4[3];
            }
            #pragma unroll
            for (int i = 0; i < 4; i++)
                #pragma unroll
                for (int j = 0; j < 8; j++)
                    mma16816(acc[i][j], ah[i], bf[j]);
        }
        __syncthreads();
        if (tid == 0) {
            if (s + 3 < 36) issueA(s + 3);
            if (khw == 8 && chunk < 3) issueHalo(chunk + 1);
        }
    }

    float* dst = out + (size_t)b * ND * NPIX;
    #pragma unroll
    for (int i = 0; i < 4; i++) {
        const int r0 = o0 + wm * 64 + i * 16 + (lane >> 2);
        const float sc0 = gamma[r0]     * rsqrtf(bn_var[r0]     + 1e-5f);
        const float sc1 = gamma[r0 + 8] * rsqrtf(bn_var[r0 + 8] + 1e-5f);
        const float ad0 = (b_out[r0]     - bn_mean[r0])     * sc0 + beta[r0];
        const float ad1 = (b_out[r0 + 8] - bn_mean[r0 + 8]) * sc1 + beta[r0 + 8];
        #pragma unroll
        for (int j = 0; j < 8; j++) {
            const int cb = n0 + wn * 64 + j * 8 + 2 * (lane & 3);
            float t0 = acc[i][j][0] * sc0 + ad0;
            float t1 = acc[i][j][1] * sc0 + ad0;
            float t2 = acc[i][j][2] * sc1 + ad1;
            float t3 = acc[i][j][3] * sc1 + ad1;
            float2 v0 = make_float2((t0 >= 0.f) ? t0 : 0.2f * t0,
                                    (t1 >= 0.f) ? t1 : 0.2f * t1);
            float2 v1 = make_float2((t2 >= 0.f) ? t2 : 0.2f * t2,
                                    (t3 >= 0.f) ? t3 : 0.2f * t3);
            *(float2*)(dst + (size_t)r0 * NPIX + cb) = v0;
            *(float2*)(dst + (size_t)(r0 + 8) * NPIX + cb) = v1;
        }
    }
}

extern "C" void kernel_launch(void* const* d_in, const int* in_sizes, int n_in,
                              void* d_out, int out_size)
{
    const float* x       = (const float*)d_in[0];
    const float* wq      = (const float*)d_in[1];
    const float* bq      = (const float*)d_in[2];
    const float* wk      = (const float*)d_in[3];
    const float* bk      = (const float*)d_in[4];
    const float* wv      = (const float*)d_in[5];
    const float* bv      = (const float*)d_in[6];
    const float* w_out   = (const float*)d_in[7];
    const float* b_out   = (const float*)d_in[8];
    const float* gamma   = (const float*)d_in[9];
    const float* beta    = (const float*)d_in[10];
    const float* bn_mean = (const float*)d_in[11];
    const float* bn_var  = (const float*)d_in[12];
    float* out = (float*)d_out;

    cudaFuncSetAttribute(qkv_mma_kernel,    cudaFuncAttributeMaxDynamicSharedMemorySize, QKV_SMEM);
    cudaFuncSetAttribute(scores_mma_kernel, cudaFuncAttributeMaxDynamicSharedMemorySize, SC_SMEM);
    cudaFuncSetAttribute(av_mma_kernel,     cudaFuncAttributeMaxDynamicSharedMemorySize, AV_SMEM);
    cudaFuncSetAttribute(conv_mma_kernel,   cudaFuncAttributeMaxDynamicSharedMemorySize, CV_SMEM);

    convert_wqkv_kernel <<<768,  256>>>(wq, wk, wv);
    convert_wconv_kernel<<<2304, 256>>>(w_out);
    convert_x_kernel<<<dim3(128, 8, 16), 256>>>(x);

    qkv_mma_kernel<<<dim3(32, 2, 16), 128, QKV_SMEM>>>(bq, bk, bv);

    scores_mma_kernel<<<dim3(16, 16), 256, SC_SMEM>>>();
    softmax_kernel<<<128, 256>>>();
    av_mma_kernel<<<dim3(64, 16), 256, AV_SMEM>>>();

    conv_mma_kernel<<<dim3(32, 2, 16), 128, CV_SMEM>>>(b_out, gamma, beta, bn_mean, bn_var, out);
}

// round 17
// speedup vs baseline: 1.1342x; 1.0117x over previous
#include <cuda_runtime.h>
#include <cuda_fp16.h>
#include <cstdint>
#include <math.h>

#define NB 16
#define ND 256
#define NPIX 4096

__device__ float g_spart[NB*16*64*64];
__device__ __align__(16) __half g_attn_h[NB*64*64];
__device__ __align__(16) __half g_attn_l[NB*64*64];

// token-major, e = o*64 + l  (o = channel, l = in-patch position)
__device__ __align__(16) __half g_qt [NB*64*16384];
__device__ __align__(16) __half g_kt [NB*64*16384];
__device__ __align__(16) __half g_vt [NB*64*16384];
__device__ __align__(16) __half g_vtl[NB*64*16384];
__device__ __align__(16) __half g_xt2 [NB*4*NPIX*64];
__device__ __align__(16) __half g_aot2[NB*4*NPIX*64];
__device__ __align__(16) __half g_wp2 [3*2*4*128*64];
__device__ __align__(16) __half g_wc2 [9*2*4*128*64];

__device__ __forceinline__ uint32_t smem_u32(const void* p){
    uint32_t a;
    asm("{ .reg .u64 t; cvta.to.shared.u64 t, %1; cvt.u32.u64 %0, t; }" : "=r"(a) : "l"(p));
    return a;
}
#define MB_INIT(mb, n) asm volatile("mbarrier.init.shared.b64 [%0], %1;" :: "r"(mb), "r"(n) : "memory")
#define MB_EXPECT(mb, bytes) asm volatile("mbarrier.arrive.expect_tx.shared.b64 _, [%0], %1;" :: "r"(mb), "r"(bytes) : "memory")

__device__ __forceinline__ void bulk_g2s(uint32_t dst, const void* src, uint32_t bytes, uint32_t mbar){
    asm volatile("{ .reg .u64 g; cvta.to.global.u64 g, %1;\n\t"
        "cp.async.bulk.shared::cluster.global.mbarrier::complete_tx::bytes [%0], [g], %2, [%3]; }"
        :: "r"(dst), "l"(src), "r"(bytes), "r"(mbar) : "memory");
}

#define MB_WAIT(mb, ph) do { \
    uint32_t _m = (mb); uint32_t _p = (uint32_t)(ph); uint32_t _d; \
    asm volatile("{\n\t.reg .pred p;\n\t" \
        "mbarrier.try_wait.parity.acquire.cta.shared::cta.b64 p, [%1], %2;\n\t" \
        "selp.b32 %0, 1, 0, p;\n\t}" : "=r"(_d) : "r"(_m), "r"(_p) : "memory"); \
    if (!_d) { \
        asm volatile("{\n\t.reg .pred P1;\n\t" \
            "WAIT_LOOP_%=:\n\t" \
            "mbarrier.try_wait.parity.acquire.cta.shared::cta.b64 P1, [%0], %1, 0x989680;\n\t" \
            "@P1 bra.uni WAIT_DONE_%=;\n\t" \
            "bra.uni WAIT_LOOP_%=;\n\t" \
            "WAIT_DONE_%=:\n\t}" :: "r"(_m), "r"(_p) : "memory"); \
    } \
} while(0)

__device__ __forceinline__ void cp16(uint32_t saddr, const void* gaddr){
    asm volatile("cp.async.ca.shared.global [%0], [%1], 16;"
        :: "r"(saddr), "l"(gaddr));
}
#define CP_COMMIT() asm volatile("cp.async.commit_group;" ::: "memory")
#define CP_WAIT1()  asm volatile("cp.async.wait_group 1;" ::: "memory")
#define CP_WAIT0()  asm volatile("cp.async.wait_group 0;" ::: "memory")

__device__ __forceinline__ void ldmat4(uint32_t* r, uint32_t addr){
    asm volatile("ldmatrix.sync.aligned.m8n8.x4.shared.b16 {%0,%1,%2,%3}, [%4];"
        : "=r"(r[0]), "=r"(r[1]), "=r"(r[2]), "=r"(r[3]) : "r"(addr));
}
__device__ __forceinline__ void ldmat4t(uint32_t* r, uint32_t addr){
    asm volatile("ldmatrix.sync.aligned.m8n8.x4.trans.shared.b16 {%0,%1,%2,%3}, [%4];"
        : "=r"(r[0]), "=r"(r[1]), "=r"(r[2]), "=r"(r[3]) : "r"(addr));
}
__device__ __forceinline__ void mma16816(float* d, const uint32_t* a, const uint32_t* b){
    asm volatile("mma.sync.aligned.m16n8k16.row.col.f32.f16.f16.f32 "
        "{%0,%1,%2,%3}, {%4,%5,%6,%7}, {%8,%9}, {%0,%1,%2,%3};"
        : "+f"(d[0]), "+f"(d[1]), "+f"(d[2]), "+f"(d[3])
        : "r"(a[0]), "r"(a[1]), "r"(a[2]), "r"(a[3]), "r"(b[0]), "r"(b[1]));
}

__global__ void __launch_bounds__(256) convert_x_kernel(const float* __restrict__ xsrc)
{
    const int b = blockIdx.z, c0 = blockIdx.y * 32, p0 = blockIdx.x * 32;
    __shared__ float tile[32][33];
    const int tx = threadIdx.x & 31, ty = threadIdx.x >> 5;
    const float* s = xsrc + ((size_t)b * ND + c0) * NPIX + p0;
    #pragma unroll
    for (int i = 0; i < 32; i += 8)
        tile[ty + i][tx] = s[(size_t)(ty + i) * NPIX + tx];
    __syncthreads();
    const int cc = (threadIdx.x & 15) * 2;
    const int pr = threadIdx.x >> 4;
    #pragma unroll
    for (int pass = 0; pass < 2; pass++) {
        const int prow = pr + pass * 16;
        const int pix = p0 + prow;
        const int c = c0 + cc;
        const int chunk = c >> 6, cl = c & 63;
        size_t di = ((size_t)(b * 4 + chunk) * NPIX + pix) * 64
                  + (((cl >> 3) ^ (pix & 7)) << 3) + (cl & 7);
        *(__half2*)(g_xt2 + di) = __floats2half2_rn(tile[cc][prow], tile[cc + 1][prow]);
    }
}

__global__ void __launch_bounds__(256) convert_wqkv_kernel(
    const float* __restrict__ wq, const float* __restrict__ wk, const float* __restrict__ wv)
{
    int i = blockIdx.x * 256 + threadIdx.x;
    const float* w = (i < 65536) ? wq : (i < 131072) ? wk : wv;
    const float v = w[i & 65535];
    const int proj = i >> 16, r = i & 65535;
    const int o_g = r >> 8, c_g = r & 255;
    const int otile = o_g >> 7, o = o_g & 127, chunk = c_g >> 6, c = c_g & 63;
    const size_t pos = (size_t)(((proj * 2 + otile) * 4 + chunk)) * 8192
                     + (o << 6) + (((c >> 3) ^ (o & 7)) << 3) + (c & 7);
    g_wp2[pos] = __float2half_rn(v);
}

__global__ void __launch_bounds__(256) convert_wconv_kernel(const float* __restrict__ w_out)
{
    int i = blockIdx.x * 256 + threadIdx.x;
    const float v = w_out[i];
    const int o_g = i / 2304;
    const int rem = i - o_g * 2304;
    const int c_g = rem / 9, khw = rem - (rem / 9) * 9;
    const int otile = o_g >> 7, o = o_g & 127, chunk = c_g >> 6, c = c_g & 63;
    const size_t pos = (size_t)(((khw * 2 + otile) * 4 + chunk)) * 8192
                     + (o << 6) + (((c >> 3) ^ (o & 7)) << 3) + (c & 7);
    g_wc2[pos] = __float2half_rn(v);
}

// ---------------- QKV GEMM: 128 thr, 64x64 warp tiles, resident B, 3 proj/CTA ----------------
#define QKV_B_OFF  1024
#define QKV_A_OFF  (1024 + 65536)
#define QKV_A_SLOT 16384
#define QKV_SMEM   (1024 + 65536 + 2*QKV_A_SLOT)

__global__ void __launch_bounds__(128, 2) qkv_mma_kernel(
    const float* __restrict__ bq, const float* __restrict__ bk, const float* __restrict__ bv)
{
    extern __shared__ char smem[];
    const uint32_t sb = smem_u32(smem);
    const uint32_t bdata = sb + QKV_B_OFF;
    const uint32_t adata = sb + QKV_A_OFF;
    const int tid = threadIdx.x;
    const int lane = tid & 31, wid = tid >> 5;
    const int wm = wid >> 1, wn = wid & 1;
    const int n0 = blockIdx.x * 128;
    const int otile = blockIdx.y, o0 = otile * 128;
    const int b = blockIdx.z;

    if (tid == 0) { MB_INIT(sb, 1); MB_INIT(sb + 8, 1); MB_INIT(sb + 16, 1); }
    __syncthreads();

    auto issueA = [&](int s) {
        const int proj = s >> 2, ck = s & 3;
        const uint32_t mb = sb + (s & 1) * 8;
        MB_EXPECT(mb, 16384u);
        bulk_g2s(adata + (s & 1) * QKV_A_SLOT,
                 g_wp2 + (size_t)((proj * 2 + otile) * 4 + ck) * 8192, 16384u, mb);
    };
    if (tid == 0) {
        MB_EXPECT(sb + 16, 65536u);
        #pragma unroll
        for (int ck = 0; ck < 4; ck++)
            bulk_g2s(bdata + ck * 16384,
                     g_xt2 + ((size_t)(b * 4 + ck) * NPIX + n0) * 64, 16384u, sb + 16);
        issueA(0); issueA(1);
    }

    float acc[4][8][4];
    #pragma unroll
    for (int i = 0; i < 4; i++)
        #pragma unroll
        for (int j = 0; j < 8; j++)
            #pragma unroll
            for (int q = 0; q < 4; q++) acc[i][j][q] = 0.f;

    #pragma unroll 1
    for (int s = 0; s < 12; s++) {
        MB_WAIT(sb + (s & 1) * 8, (s >> 1) & 1);
        if (s == 0) MB_WAIT(sb + 16, 0);
        const uint32_t ab = adata + (s & 1) * QKV_A_SLOT;
        const uint32_t bb = bdata + (s & 3) * 16384;
        #pragma unroll
        for (int kh = 0; kh < 4; kh++) {
            uint32_t ah[4][4], bf[8][2];
            #pragma unroll
            for (int i = 0; i < 4; i++) {
                const int row = wm * 64 + i * 16 + (lane & 15);
                const int ch = (2 * kh + (lane >> 4)) ^ (row & 7);
                ldmat4(ah[i], ab + row * 128 + ch * 16);
            }
            #pragma unroll
            for (int jj = 0; jj < 4; jj++) {
                const int row = wn * 64 + jj * 16 + (lane & 7) + ((lane >> 4) << 3);
                const int ch = (2 * kh + ((lane >> 3) & 1)) ^ (row & 7);
                uint32_t r4[4];
                ldmat4(r4, bb + row * 128 + ch * 16);
                bf[2*jj][0] = r4[0]; bf[2*jj][1] = r4[1];
                bf[2*jj+1][0] = r4[2]; bf[2*jj+1][1] = r4[3];
            }
            #pragma unroll
            for (int i = 0; i < 4; i++)
                #pragma unroll
                for (int j = 0; j < 8; j++)
                    mma16816(acc[i][j], ah[i], bf[j]);
        }
        __syncthreads();
        if (tid == 0 && s + 2 < 12) issueA(s + 2);

        if ((s & 3) == 3) {
            const int proj = s >> 2;
            const float* bias = (proj == 0) ? bq : (proj == 1) ? bk : bv;
            if (proj < 2) {
                __half* qt = ((proj == 0) ? g_qt : g_kt) + (size_t)b * 64 * 16384;
                #pragma unroll
                for (int i = 0; i < 4; i++) {
                    const int r0 = o0 + wm * 64 + i * 16 + (lane >> 2);
                    const float bb0 = bias[r0], bb1 = bias[r0 + 8];
                    #pragma unroll
                    for (int j = 0; j < 8; j++) {
                        const int p = n0 + wn * 64 + j * 8 + 2 * (lane & 3);
                        const int h = p >> 6, w = p & 63;
                        const int t = ((h >> 3) << 3) + (w >> 3);
                        const int l = ((h & 7) << 3) + (w & 7);
                        __half2 v0 = __floats2half2_rn(acc[i][j][0] + bb0, acc[i][j][1] + bb0);
                        __half2 v1 = __floats2half2_rn(acc[i][j][2] + bb1, acc[i][j][3] + bb1);
                        *(__half2*)(qt + (size_t)t * 16384 + r0 * 64 + l) = v0;
                        *(__half2*)(qt + (size_t)t * 16384 + (r0 + 8) * 64 + l) = v1;
                        #pragma unroll
                        for (int q = 0; q < 4; q++) acc[i][j][q] = 0.f;
                    }
                }
            } else {
                __half* vh = g_vt  + (size_t)b * 64 * 16384;
                __half* vl = g_vtl + (size_t)b * 64 * 16384;
                #pragma unroll
                for (int i = 0; i < 4; i++) {
                    const int r0 = o0 + wm * 64 + i * 16 + (lane >> 2);
                    const float bb0 = bias[r0], bb1 = bias[r0 + 8];
                    #pragma unroll
                    for (int j = 0; j < 8; j++) {
                        const int p = n0 + wn * 64 + j * 8 + 2 * (lane & 3);
                        const int h = p >> 6, w = p & 63;
                        const int t = ((h >> 3) << 3) + (w >> 3);
                        const int l = ((h & 7) << 3) + (w & 7);
                        float f0 = acc[i][j][0] + bb0, f1 = acc[i][j][1] + bb0;
                        float f2 = acc[i][j][2] + bb1, f3 = acc[i][j][3] + bb1;
                        __half h0 = __float2half_rn(f0), h1 = __float2half_rn(f1);
                        __half h2 = __float2half_rn(f2), h3 = __float2half_rn(f3);
                        __half2 hv0; hv0.x = h0; hv0.y = h1;
                        __half2 hv1; hv1.x = h2; hv1.y = h3;
                        __half2 lv0 = __floats2half2_rn(f0 - __half2float(h0), f1 - __half2float(h1));
                        __half2 lv1 = __floats2half2_rn(f2 - __half2float(h2), f3 - __half2float(h3));
                        *(__half2*)(vh + (size_t)t * 16384 + r0 * 64 + l) = hv0;
                        *(__half2*)(vh + (size_t)t * 16384 + (r0 + 8) * 64 + l) = hv1;
                        *(__half2*)(vl + (size_t)t * 16384 + r0 * 64 + l) = lv0;
                        *(__half2*)(vl + (size_t)t * 16384 + (r0 + 8) * 64 + l) = lv1;
                    }
                }
            }
        }
    }
}

// ---------------- scores via mma: 16 e-slices of 1024 ----------------
#define SC_STAGE 16384
#define SC_SMEM  (3*SC_STAGE)

__global__ void __launch_bounds__(256, 2) scores_mma_kernel()
{
    extern __shared__ char smem[];
    const uint32_t sbase = smem_u32(smem);
    const int tid = threadIdx.x;
    const int lane = tid & 31, wid = tid >> 5;
    const int wm = wid & 3, wn = wid >> 2;
    const int slice = blockIdx.x, b = blockIdx.y;
    const size_t eoff = (size_t)slice * 1024;

    const __half* Q = g_qt + (size_t)b * 64 * 16384 + eoff;
    const __half* K = g_kt + (size_t)b * 64 * 16384 + eoff;

    auto load_stage = [&](int ck, int buf) {
        const uint32_t stb = sbase + buf * SC_STAGE;
        #pragma unroll
        for (int q = 0; q < 2; q++) {
            const int idx = tid + q * 256;
            const int row = idx >> 3, c = idx & 7;
            const uint32_t so = row * 128 + ((c ^ (row & 7)) << 4);
            const size_t goff = (size_t)row * 16384 + ck * 64 + c * 8;
            cp16(stb + so,        Q + goff);
            cp16(stb + 8192 + so, K + goff);
        }
        CP_COMMIT();
    };

    float acc[4][4];
    #pragma unroll
    for (int j = 0; j < 4; j++)
        #pragma unroll
        for (int q = 0; q < 4; q++) acc[j][q] = 0.f;

    load_stage(0, 0);
    load_stage(1, 1);
    #pragma unroll 1
    for (int s = 0; s < 16; s++) {
        if (s + 1 < 16) { CP_WAIT1(); } else { CP_WAIT0(); }
        __syncthreads();
        if (s + 2 < 16) load_stage(s + 2, (s + 2) % 3);
        const uint32_t qb = sbase + (s % 3) * SC_STAGE;
        const uint32_t kb = qb + 8192;
        #pragma unroll
        for (int kh = 0; kh < 4; kh++) {
            uint32_t ah[4], bf[4][2];
            {
                const int row = wm * 16 + (lane & 15);
                const int ch = (2 * kh + (lane >> 4)) ^ (row & 7);
                ldmat4(ah, qb + row * 128 + ch * 16);
            }
            #pragma unroll
            for (int jj = 0; jj < 2; jj++) {
                const int row = wn * 32 + jj * 16 + (lane & 7) + ((lane >> 4) << 3);
                const int ch = (2 * kh + ((lane >> 3) & 1)) ^ (row & 7);
                uint32_t r4[4];
                ldmat4(r4, kb + row * 128 + ch * 16);
                bf[2*jj][0] = r4[0]; bf[2*jj][1] = r4[1];
                bf[2*jj+1][0] = r4[2]; bf[2*jj+1][1] = r4[3];
            }
            #pragma unroll
            for (int j = 0; j < 4; j++)
                mma16816(acc[j], ah, bf[j]);
        }
        __syncthreads();
    }

    float* dst = g_spart + ((size_t)(b * 16 + slice)) * 4096;
    #pragma unroll
    for (int j = 0; j < 4; j++) {
        const int r0 = wm * 16 + (lane >> 2);
        const int cb = wn * 32 + j * 8 + 2 * (lane & 3);
        *(float2*)(dst + r0 * 64 + cb)       = make_float2(acc[j][0], acc[j][1]);
        *(float2*)(dst + (r0 + 8) * 64 + cb) = make_float2(acc[j][2], acc[j][3]);
    }
}

// ---------------- softmax: warp-per-row ----------------
__global__ void __launch_bounds__(256) softmax_kernel()
{
    const int g = blockIdx.x * 8 + (threadIdx.x >> 5);
    const int lane = threadIdx.x & 31;
    const int b = g >> 6, t = g & 63;
    const int c0 = lane * 2;
    const float scale = 1.0f / 128.0f;

    float v0 = 0.f, v1 = 0.f;
    const float* base = g_spart + (size_t)(b * 16) * 4096 + t * 64 + c0;
    #pragma unroll
    for (int sl = 0; sl < 16; sl++) {
        const float2 p = *(const float2*)(base + (size_t)sl * 4096);
        v0 += p.x; v1 += p.y;
    }
    v0 *= scale; v1 *= scale;
    float m = fmaxf(v0, v1);
    #pragma unroll
    for (int o = 16; o > 0; o >>= 1)
        m = fmaxf(m, __shfl_xor_sync(0xffffffffu, m, o));
    v0 = __expf(v0 - m); v1 = __expf(v1 - m);
    float s = v0 + v1;
    #pragma unroll
    for (int o = 16; o > 0; o >>= 1)
        s += __shfl_xor_sync(0xffffffffu, s, o);
    const float inv = 1.0f / s;
    const float f0 = v0 * inv, f1 = v1 * inv;
    const __half h0 = __float2half_rn(f0), h1 = __float2half_rn(f1);
    __half2 hh; hh.x = h0; hh.y = h1;
    *(__half2*)(g_attn_h + b * 4096 + t * 64 + c0) = hh;
    *(__half2*)(g_attn_l + b * 4096 + t * 64 + c0) =
        __floats2half2_rn(f0 - __half2float(h0), f1 - __half2float(h1));
}

#define AV_AL   8192
#define AV_VH   16384
#define AV_VL   49152
#define AV_OUT  81920
#define AV_SMEM 114688

__global__ void __launch_bounds__(256, 2) av_mma_kernel()
{
    extern __shared__ char smem[];
    const uint32_t sbase = smem_u32(smem);
    const int tid = threadIdx.x;
    const int lane = tid & 31, wid = tid >> 5;
    const int wm = wid >> 1, wn = wid & 1;
    const int et = blockIdx.x, b = blockIdx.y;
    const size_t e0 = (size_t)et * 256;

    {
        const __half* Ah = g_attn_h + (size_t)b * 4096;
        const __half* Al = g_attn_l + (size_t)b * 4096;
        const __half* Vh = g_vt  + (size_t)b * 64 * 16384 + e0;
        const __half* Vl = g_vtl + (size_t)b * 64 * 16384 + e0;
        #pragma unroll
        for (int q = 0; q < 2; q++) {
            const int idx = tid + q * 256;
            const int row = idx >> 3, c = idx & 7;
            const uint32_t so = row * 128 + ((c ^ (row & 7)) << 4);
            cp16(sbase + so,         Ah + (size_t)row * 64 + c * 8);
            cp16(sbase + AV_AL + so, Al + (size_t)row * 64 + c * 8);
        }
        #pragma unroll
        for (int q = 0; q < 8; q++) {
            const int idx = tid + q * 256;
            const int row = idx >> 5, c = idx & 31;
            const int sw = (c & 24) | ((c & 7) ^ (row & 7));
            cp16(sbase + AV_VH + row * 512 + sw * 16, Vh + (size_t)row * 16384 + c * 8);
            cp16(sbase + AV_VL + row * 512 + sw * 16, Vl + (size_t)row * 16384 + c * 8);
        }
        CP_COMMIT();
        CP_WAIT0();
    }
    __syncthreads();

    float acc[16][4];
    #pragma unroll
    for (int j = 0; j < 16; j++)
        #pragma unroll
        for (int q = 0; q < 4; q++) acc[j][q] = 0.f;

    #pragma unroll
    for (int kh = 0; kh < 4; kh++) {
        uint32_t ahh[4], ahl[4];
        {
            const int row = wm * 16 + (lane & 15);
            const int ch = (2 * kh + (lane >> 4)) ^ (row & 7);
            ldmat4(ahh, sbase + row * 128 + ch * 16);
            ldmat4(ahl, sbase + AV_AL + row * 128 + ch * 16);
        }
        #pragma unroll
        for (int jj = 0; jj < 8; jj++) {
            const int u = kh * 16 + (lane & 15);
            const int c32 = wn * 16 + jj * 2 + (lane >> 4);
            const int sw = (c32 & 24) | ((c32 & 7) ^ (u & 7));
            uint32_t rh[4], rl[4];
            ldmat4t(rh, sbase + AV_VH + u * 512 + sw * 16);
            ldmat4t(rl, sbase + AV_VL + u * 512 + sw * 16);
            uint32_t bh0[2] = { rh[0], rh[1] }, bh1[2] = { rh[2], rh[3] };
            uint32_t bl0[2] = { rl[0], rl[1] }, bl1[2] = { rl[2], rl[3] };
            mma16816(acc[jj*2],   ahh, bh0);
            mma16816(acc[jj*2],   ahh, bl0);
            mma16816(acc[jj*2],   ahl, bh0);
            mma16816(acc[jj*2],   ahl, bl0);
            mma16816(acc[jj*2+1], ahh, bh1);
            mma16816(acc[jj*2+1], ahh, bl1);
            mma16816(acc[jj*2+1], ahl, bh1);
            mma16816(acc[jj*2+1], ahl, bl1);
        }
    }

    #pragma unroll
    for (int j = 0; j < 16; j++) {
        const int t0 = wm * 16 + (lane >> 2);
        const int e  = wn * 128 + j * 8 + 2 * (lane & 3);
        const int c  = e >> 3;
        const int sw0 = (c & 24) | ((c & 7) ^ (t0 & 7));
        const int sw1 = (c & 24) | ((c & 7) ^ ((t0 + 8) & 7));
        __half2 v0 = __floats2half2_rn(acc[j][0], acc[j][1]);
        __half2 v1 = __floats2half2_rn(acc[j][2], acc[j][3]);
        *(__half2*)(smem + AV_OUT + t0 * 512 + sw0 * 16 + (e & 7) * 2) = v0;
        *(__half2*)(smem + AV_OUT + (t0 + 8) * 512 + sw1 * 16 + (e & 7) * 2) = v1;
    }
    __syncthreads();

    const int d0g = et * 4;
    const int chunk_g = d0g >> 6, cl0 = d0g & 63;
    __half* outg = g_aot2 + ((size_t)(b * 4 + chunk_g)) * NPIX * 64;
    #pragma unroll
    for (int p = 0; p < 16; p++) {
        const int pix = tid + p * 256;
        const int h = pix >> 6, w = pix & 63;
        const int t = ((h >> 3) << 3) + (w >> 3);
        const int l = ((h & 7) << 3) + (w & 7);
        uint32_t hv[4];
        #pragma unroll
        for (int dq = 0; dq < 4; dq++) {
            const int sw = dq * 8 + ((l >> 3) ^ (t & 7));
            hv[dq] = *(const uint16_t*)(smem + AV_OUT + t * 512 + sw * 16 + (l & 7) * 2);
        }
        uint2 pk;
        pk.x = hv[0] | (hv[1] << 16);
        pk.y = hv[2] | (hv[3] << 16);
        const size_t off = (size_t)pix * 64 + (((cl0 >> 3) ^ (pix & 7)) << 3) + (cl0 & 7);
        *(uint2*)(outg + off) = pk;
    }
}

// ---------------- conv 3x3: khw-paired stages (20 barriers), BN + LeakyReLU ----------------
#define CV_A_SLOT  32768
#define CV_HALO    (1024 + 2*CV_A_SLOT)
#define CV_SMEM    (CV_HALO + 33792)

__global__ void __launch_bounds__(128, 2) conv_mma_kernel(
    const float* __restrict__ b_out, const float* __restrict__ gamma,
    const float* __restrict__ beta,  const float* __restrict__ bn_mean,
    const float* __restrict__ bn_var, float* __restrict__ out)
{
    extern __shared__ char smem[];
    const uint32_t sb = smem_u32(smem);
    const uint32_t data = sb + 1024;
    const uint32_t halo = sb + CV_HALO;
    const int tid = threadIdx.x;
    const int lane = tid & 31, wid = tid >> 5;
    const int wm = wid >> 1, wn = wid & 1;
    const int pt = blockIdx.x;
    const int otile = blockIdx.y, o0 = otile * 128;
    const int b = blockIdx.z;
    const int h0 = pt * 2, n0 = pt * 128;

    const __half* Bbase = g_aot2 + (size_t)(b * 4) * NPIX * 64;

    if (tid == 0) { MB_INIT(sb, 1); MB_INIT(sb + 8, 1); MB_INIT(sb + 24, 1); }
    {
        const int4 z = make_int4(0, 0, 0, 0);
        for (int idx = tid; idx < 2112; idx += 128)
            *(int4*)(smem + CV_HALO + idx * 16) = z;
    }
    __syncthreads();

    // stage t = chunk*5 + sp; sp<4 covers khw {2sp, 2sp+1}, sp==4 covers khw 8
    auto issueA = [&](int t) {
        const int chunk = t / 5, sp = t % 5;
        const int nkh = (sp < 4) ? 2 : 1;
        const uint32_t mb = sb + (t & 1) * 8;
        MB_EXPECT(mb, (uint32_t)(nkh * 16384));
        #pragma unroll
        for (int k2 = 0; k2 < 2; k2++) {
            if (k2 < nkh) {
                const int khw = sp * 2 + k2;
                bulk_g2s(data + (t & 1) * CV_A_SLOT + k2 * 16384,
                         g_wc2 + (size_t)((khw * 2 + otile) * 4 + chunk) * 8192, 16384u, mb);
            }
        }
    };
    auto issueHalo = [&](int chunk) {
        const uint32_t mb = sb + 24;
        uint32_t bytes = 0;
        #pragma unroll
        for (int hr = 0; hr < 4; hr++) {
            const int h2 = h0 - 1 + hr;
            if ((unsigned)h2 < 64u) bytes += 8192u;
        }
        MB_EXPECT(mb, bytes);
        #pragma unroll
        for (int hr = 0; hr < 4; hr++) {
            const int h2 = h0 - 1 + hr;
            if ((unsigned)h2 < 64u)
                bulk_g2s(halo + hr * 8448 + 128,
                         Bbase + ((size_t)chunk * NPIX + h2 * 64) * 64, 8192u, mb);
        }
    };
    if (tid == 0) { issueHalo(0); issueA(0); issueA(1); }

    float acc[4][8][4];
    #pragma unroll
    for (int i = 0; i < 4; i++)
        #pragma unroll
        for (int j = 0; j < 8; j++)
            #pragma unroll
            for (int q = 0; q < 4; q++) acc[i][j][q] = 0.f;

    #pragma unroll 1
    for (int t = 0; t < 20; t++) {
        const int chunk = t / 5, sp = t % 5;
        const int nkh = (sp < 4) ? 2 : 1;
        MB_WAIT(sb + (t & 1) * 8, (t >> 1) & 1);
        if (sp == 0) MB_WAIT(sb + 24, chunk & 1);
        #pragma unroll 1
        for (int k2 = 0; k2 < nkh; k2++) {
            const int khw = sp * 2 + k2;
            const int dh = khw / 3 - 1, dw = khw % 3 - 1;
            const uint32_t ab = data + (t & 1) * CV_A_SLOT + k2 * 16384;
            #pragma unroll
            for (int kh = 0; kh < 4; kh++) {
                uint32_t ah[4][4], bf[8][2];
                #pragma unroll
                for (int i = 0; i < 4; i++) {
                    const int row = wm * 64 + i * 16 + (lane & 15);
                    const int ch = (2 * kh + (lane >> 4)) ^ (row & 7);
                    ldmat4(ah[i], ab + row * 128 + ch * 16);
                }
                #pragma unroll
                for (int jj = 0; jj < 4; jj++) {
                    const int p = wn * 64 + jj * 16 + (lane & 7) + ((lane >> 4) << 3);
                    const int w2 = (p & 63) + dw;
                    const int er = (p >> 6) + dh + 1;
                    const int e = er * 66 + w2 + 1;
                    const int ch = (2 * kh + ((lane >> 3) & 1)) ^ (w2 & 7);
                    uint32_t r4[4];
                    ldmat4(r4, halo + e * 128 + ch * 16);
                    bf[2*jj][0] = r4[0]; bf[2*jj][1] = r4[1];
                    bf[2*jj+1][0] = r4[2]; bf[2*jj+1][1] = r4[3];
                }
                #pragma unroll
                for (int i = 0; i < 4; i++)
                    #pragma unroll
                    for (int j = 0; j < 8; j++)
                        mma16816(acc[i][j], ah[i], bf[j]);
            }
        }
        __syncthreads();
        if (tid == 0) {
            if (t + 2 < 20) issueA(t + 2);
            if (sp == 4 && chunk < 3) issueHalo(chunk + 1);
        }
    }

    float* dst = out + (size_t)b * ND * NPIX;
    #pragma unroll
    for (int i = 0; i < 4; i++) {
        const int r0 = o0 + wm * 64 + i * 16 + (lane >> 2);
        const float sc0 = gamma[r0]     * rsqrtf(bn_var[r0]     + 1e-5f);
        const float sc1 = gamma[r0 + 8] * rsqrtf(bn_var[r0 + 8] + 1e-5f);
        const float ad0 = (b_out[r0]     - bn_mean[r0])     * sc0 + beta[r0];
        const float ad1 = (b_out[r0 + 8] - bn_mean[r0 + 8]) * sc1 + beta[r0 + 8];
        #pragma unroll
        for (int j = 0; j < 8; j++) {
            const int cb = n0 + wn * 64 + j * 8 + 2 * (lane & 3);
            float t0 = acc[i][j][0] * sc0 + ad0;
            float t1 = acc[i][j][1] * sc0 + ad0;
            float t2 = acc[i][j][2] * sc1 + ad1;
            float t3 = acc[i][j][3] * sc1 + ad1;
            float2 v0 = make_float2((t0 >= 0.f) ? t0 : 0.2f * t0,
                                    (t1 >= 0.f) ? t1 : 0.2f * t1);
            float2 v1 = make_float2((t2 >= 0.f) ? t2 : 0.2f * t2,
                                    (t3 >= 0.f) ? t3 : 0.2f * t3);
            *(float2*)(dst + (size_t)r0 * NPIX + cb) = v0;
            *(float2*)(dst + (size_t)(r0 + 8) * NPIX + cb) = v1;
        }
    }
}

extern "C" void kernel_launch(void* const* d_in, const int* in_sizes, int n_in,
                              void* d_out, int out_size)
{
    const float* x       = (const float*)d_in[0];
    const float* wq      = (const float*)d_in[1];
    const float* bq      = (const float*)d_in[2];
    const float* wk      = (const float*)d_in[3];
    const float* bk      = (const float*)d_in[4];
    const float* wv      = (const float*)d_in[5];
    const float* bv      = (const float*)d_in[6];
    const float* w_out   = (const float*)d_in[7];
    const float* b_out   = (const float*)d_in[8];
    const float* gamma   = (const float*)d_in[9];
    const float* beta    = (const float*)d_in[10];
    const float* bn_mean = (const float*)d_in[11];
    const float* bn_var  = (const float*)d_in[12];
    float* out = (float*)d_out;

    cudaFuncSetAttribute(qkv_mma_kernel,    cudaFuncAttributeMaxDynamicSharedMemorySize, QKV_SMEM);
    cudaFuncSetAttribute(scores_mma_kernel, cudaFuncAttributeMaxDynamicSharedMemorySize, SC_SMEM);
    cudaFuncSetAttribute(av_mma_kernel,     cudaFuncAttributeMaxDynamicSharedMemorySize, AV_SMEM);
    cudaFuncSetAttribute(conv_mma_kernel,   cudaFuncAttributeMaxDynamicSharedMemorySize, CV_SMEM);

    convert_wqkv_kernel <<<768,  256>>>(wq, wk, wv);
    convert_wconv_kernel<<<2304, 256>>>(w_out);
    convert_x_kernel<<<dim3(128, 8, 16), 256>>>(x);

    qkv_mma_kernel<<<dim3(32, 2, 16), 128, QKV_SMEM>>>(bq, bk, bv);

    scores_mma_kernel<<<dim3(16, 16), 256, SC_SMEM>>>();
    softmax_kernel<<<128, 256>>>();
    av_mma_kernel<<<dim3(64, 16), 256, AV_SMEM>>>();

    conv_mma_kernel<<<dim3(32, 2, 16), 128, CV_SMEM>>>(b_out, gamma, beta, bn_mean, bn_var, out);
}